// round 9
// baseline (speedup 1.0000x reference)
#include <cuda_runtime.h>
#include <cuda_fp16.h>
#include <cstdint>

#define N_NODES 50000
#define N_EDGES 600000
#define EDGE_BLOCKS 2344

// ---------------- scratch (static __device__, no allocations) ----------------
__device__ int      g_src[N_EDGES];
__device__ int      g_dst[N_EDGES];
__device__ int      g_csr[N_EDGES];
__device__ int      g_ideg[50048];
__device__ int      g_rowptr[N_NODES + 1];
__device__ int      g_bsum[256];
__device__ int      g_cnt[50048];
__device__ uint16_t g_xh [(size_t)N_NODES * 128];
__device__ uint16_t g_h1h[(size_t)N_NODES * 128];
__device__ uint16_t g_h2h[(size_t)N_NODES * 128];
__device__ uint16_t g_B1[128 * 256];
__device__ uint16_t g_B2[128 * 256];
__device__ uint16_t g_B3[64 * 256];

// ---------------- mma / cp.async helpers ----------------
__device__ __forceinline__ void mma_f16(float* d, const uint32_t* a, const uint32_t* b) {
    asm volatile(
        "mma.sync.aligned.m16n8k16.row.col.f32.f16.f16.f32 "
        "{%0,%1,%2,%3}, {%4,%5,%6,%7}, {%8,%9}, {%0,%1,%2,%3};"
        : "+f"(d[0]), "+f"(d[1]), "+f"(d[2]), "+f"(d[3])
        : "r"(a[0]), "r"(a[1]), "r"(a[2]), "r"(a[3]), "r"(b[0]), "r"(b[1]));
}
__device__ __forceinline__ void cp16(uint32_t smem, const void* g) {
    asm volatile("cp.async.ca.shared.global [%0], [%1], 16;" :: "r"(smem), "l"(g));
}
#define CP_COMMIT() asm volatile("cp.async.commit_group;")
#define CP_WAIT(N)  asm volatile("cp.async.wait_group %0;" :: "n"(N))

// ---------------- structure: convert + degree (block-local dtype detect) + fp16 prep ----------------
__global__ void convert_deg_prep(const void* p, const float* __restrict__ x,
                                 const float* w1n, const float* w1r,
                                 const float* w2n, const float* w2r,
                                 const float* w3n, const float* w3r) {
    int b = blockIdx.x;
    if (b < EDGE_BLOCKS) {
        // block-local dtype sniff: int64 edges have zero high words (values < 50000)
        __shared__ int cnt_s;
        if (threadIdx.x == 0) cnt_s = 0;
        __syncthreads();
        const unsigned int* p32 = (const unsigned int*)p;
        int local = 0;
#pragma unroll
        for (int i = threadIdx.x; i < 2048; i += 256)
            if (p32[2 * i + 1] == 0u) local++;
#pragma unroll
        for (int o = 16; o > 0; o >>= 1) local += __shfl_down_sync(~0u, local, o);
        if ((threadIdx.x & 31) == 0) atomicAdd(&cnt_s, local);
        __syncthreads();
        bool is64 = (cnt_s > 1024);

        int e = b * 256 + threadIdx.x;
        if (e >= N_EDGES) return;
        int s, d;
        if (is64) {
            const long long* q = (const long long*)p;
            s = (int)q[e];
            d = (int)q[N_EDGES + e];
        } else {
            const int* q = (const int*)p;
            s = q[e];
            d = q[N_EDGES + e];
        }
        g_src[e] = s;
        g_dst[e] = d;
        atomicAdd(&g_ideg[d], 1);
        return;
    }
    int i = (b - EDGE_BLOCKS) * 256 + threadIdx.x;
    const int NX = N_NODES * 64;                  // half2 count for x
    if (i < NX) {
        float2 v = ((const float2*)x)[i];
        ((__half2*)g_xh)[i] = __floats2half2_rn(v.x, v.y);
        return;
    }
    int idx = i - NX;
    if (idx < 32768) {
        int o = idx >> 8, k = idx & 255;
        float v = (k < 128) ? w1n[o * 128 + k] : w1r[o * 128 + (k - 128)];
        g_B1[idx] = __half_as_ushort(__float2half_rn(v));
    } else if (idx < 65536) {
        int j = idx - 32768;
        int o = j >> 8, k = j & 255;
        float v = (k < 128) ? w2n[o * 128 + k] : w2r[o * 128 + (k - 128)];
        g_B2[j] = __half_as_ushort(__float2half_rn(v));
    } else if (idx < 81920) {
        int j = idx - 65536;
        int o = j >> 8, k = j & 255;
        float v = (k < 128) ? w3n[o * 128 + k] : w3r[o * 128 + (k - 128)];
        g_B3[j] = __half_as_ushort(__float2half_rn(v));
    }
}

// ---- scan phase 1: per-block exclusive scan of g_ideg, block sums to g_bsum ----
__global__ void scan_local() {            // grid 196, block 256
    __shared__ int wtot[8];
    int b = blockIdx.x, t = threadIdx.x, i = b * 256 + t;
    int lane = t & 31, wid = t >> 5;
    int v = (i < N_NODES) ? g_ideg[i] : 0;
    int x = v;
#pragma unroll
    for (int o = 1; o < 32; o <<= 1) {
        int y = __shfl_up_sync(~0u, x, o);
        if (lane >= o) x += y;
    }
    if (lane == 31) wtot[wid] = x;
    __syncthreads();
    if (wid == 0) {
        int w = (lane < 8) ? wtot[lane] : 0;
#pragma unroll
        for (int o = 1; o < 8; o <<= 1) {
            int y = __shfl_up_sync(0xffffffffu, w, o);
            if (lane >= o) w += y;
        }
        if (lane < 8) wtot[lane] = w;
    }
    __syncthreads();
    int excl = x - v + (wid > 0 ? wtot[wid - 1] : 0);
    if (i < N_NODES) g_rowptr[i] = excl;
    if (t == 255) g_bsum[b] = excl + v;
}

// ---- scan phase 2 (fused): every block redundantly scans the 196 block sums, adds its offset ----
__global__ void scan_add_full() {         // grid 196, block 256
    __shared__ int sb[256];
    __shared__ int wtot[8];
    int t = threadIdx.x, lane = t & 31, wid = t >> 5;
    int v = (t < 196) ? g_bsum[t] : 0;
    int x = v;
#pragma unroll
    for (int o = 1; o < 32; o <<= 1) {
        int y = __shfl_up_sync(~0u, x, o);
        if (lane >= o) x += y;
    }
    if (lane == 31) wtot[wid] = x;
    __syncthreads();
    if (wid == 0) {
        int w = (lane < 8) ? wtot[lane] : 0;
#pragma unroll
        for (int o = 1; o < 8; o <<= 1) {
            int y = __shfl_up_sync(0xffffffffu, w, o);
            if (lane >= o) w += y;
        }
        if (lane < 8) wtot[lane] = w;
    }
    __syncthreads();
    sb[t] = x - v + (wid > 0 ? wtot[wid - 1] : 0);
    __syncthreads();
    int add = sb[blockIdx.x];
    int i = blockIdx.x * 256 + t;
    if (i < N_NODES) g_rowptr[i] += add;
    if (blockIdx.x == 0 && t == 0) g_rowptr[N_NODES] = N_EDGES;
}

__global__ void fill_csr() {
    int e = blockIdx.x * blockDim.x + threadIdx.x;
    if (e >= N_EDGES) return;
    int d = g_dst[e];
    int pos = atomicAdd(&g_cnt[d], 1);
    g_csr[g_rowptr[d] + pos] = g_src[e];
}

// ---------------- fused layer: gather-mean into smem A + tensor-core GEMM ----------------
// A-tile (64 rows x K=256 halves): cols 0..63 (u32) = neighbor mean (gathered),
//                                  cols 64..127     = root features (cp.async).
// B double-buffered per 64-half chunk. 4 warps: 2(m) x 2(n).
template <int OUT, bool RELU, bool HOUT>
__global__ void __launch_bounds__(128, 3) fused_layer(
    const uint16_t* __restrict__ Xh,
    const uint16_t* __restrict__ Bw,
    const float* __restrict__ bias,
    void* __restrict__ Cout)
{
    constexpr int NA = OUT / 16;
    __shared__ uint32_t As[64][132];
    __shared__ uint32_t Bs[2][OUT][36];

    const int tid    = threadIdx.x;
    const int wid    = tid >> 5;
    const int lane   = tid & 31;
    const int warp_m = wid >> 1;
    const int warp_n = wid & 1;
    const int g      = lane >> 2;
    const int t      = lane & 3;
    const int row0   = blockIdx.x * 64;

    // ---- issue root-half (A cols 64..127) + B chunk 0 via cp.async (overlaps gather) ----
#pragma unroll
    for (int i = 0; i < 8; i++) {                  // 64 rows x 16 uint4 / 128 thr
        int idx = i * 128 + tid;
        int r = idx >> 4, q = idx & 15;
        int grow = row0 + r;
        if (grow > N_NODES - 1) grow = N_NODES - 1;
        cp16((uint32_t)__cvta_generic_to_shared(&As[r][64 + q * 4]),
             Xh + (size_t)grow * 128 + q * 8);
    }
#pragma unroll
    for (int i = 0; i < OUT / 16; i++) {           // B chunk 0
        int idx = i * 128 + tid;
        int o = idx >> 3, q = idx & 7;
        cp16((uint32_t)__cvta_generic_to_shared(&Bs[0][o][q * 4]),
             Bw + (size_t)o * 256 + q * 8);
    }
    CP_COMMIT();

    // ---- gather: each warp aggregates 16 nodes (2 half-warps, 4-deep MLP) ----
    {
        const int half = lane >> 4;
        const int l16  = lane & 15;
#pragma unroll 1
        for (int i = 0; i < 16; i++) {
            int r = wid * 16 + i;
            int node = row0 + r;
            if (node < N_NODES) {
                int beg = g_rowptr[node], end = g_rowptr[node + 1];
                float a[8];
#pragma unroll
                for (int j = 0; j < 8; j++) a[j] = 0.f;
                int e = beg + half;
                for (; e + 6 < end; e += 8) {
                    int s0 = g_csr[e],     s1 = g_csr[e + 2];
                    int s2 = g_csr[e + 4], s3 = g_csr[e + 6];
                    uint4 u0 = ((const uint4*)(Xh + (size_t)s0 * 128))[l16];
                    uint4 u1 = ((const uint4*)(Xh + (size_t)s1 * 128))[l16];
                    uint4 u2 = ((const uint4*)(Xh + (size_t)s2 * 128))[l16];
                    uint4 u3 = ((const uint4*)(Xh + (size_t)s3 * 128))[l16];
                    float2 f;
                    f = __half22float2(*(__half2*)&u0.x); a[0] += f.x; a[1] += f.y;
                    f = __half22float2(*(__half2*)&u0.y); a[2] += f.x; a[3] += f.y;
                    f = __half22float2(*(__half2*)&u0.z); a[4] += f.x; a[5] += f.y;
                    f = __half22float2(*(__half2*)&u0.w); a[6] += f.x; a[7] += f.y;
                    f = __half22float2(*(__half2*)&u1.x); a[0] += f.x; a[1] += f.y;
                    f = __half22float2(*(__half2*)&u1.y); a[2] += f.x; a[3] += f.y;
                    f = __half22float2(*(__half2*)&u1.z); a[4] += f.x; a[5] += f.y;
                    f = __half22float2(*(__half2*)&u1.w); a[6] += f.x; a[7] += f.y;
                    f = __half22float2(*(__half2*)&u2.x); a[0] += f.x; a[1] += f.y;
                    f = __half22float2(*(__half2*)&u2.y); a[2] += f.x; a[3] += f.y;
                    f = __half22float2(*(__half2*)&u2.z); a[4] += f.x; a[5] += f.y;
                    f = __half22float2(*(__half2*)&u2.w); a[6] += f.x; a[7] += f.y;
                    f = __half22float2(*(__half2*)&u3.x); a[0] += f.x; a[1] += f.y;
                    f = __half22float2(*(__half2*)&u3.y); a[2] += f.x; a[3] += f.y;
                    f = __half22float2(*(__half2*)&u3.z); a[4] += f.x; a[5] += f.y;
                    f = __half22float2(*(__half2*)&u3.w); a[6] += f.x; a[7] += f.y;
                }
                for (; e < end; e += 2) {
                    int s = g_csr[e];
                    uint4 u = ((const uint4*)(Xh + (size_t)s * 128))[l16];
                    float2 f;
                    f = __half22float2(*(__half2*)&u.x); a[0] += f.x; a[1] += f.y;
                    f = __half22float2(*(__half2*)&u.y); a[2] += f.x; a[3] += f.y;
                    f = __half22float2(*(__half2*)&u.z); a[4] += f.x; a[5] += f.y;
                    f = __half22float2(*(__half2*)&u.w); a[6] += f.x; a[7] += f.y;
                }
#pragma unroll
                for (int j = 0; j < 8; j++) a[j] += __shfl_down_sync(~0u, a[j], 16);
                if (half == 0) {
                    float inv = 1.0f / fmaxf((float)(end - beg), 1.0f);
                    __half2 h0 = __floats2half2_rn(a[0] * inv, a[1] * inv);
                    __half2 h1 = __floats2half2_rn(a[2] * inv, a[3] * inv);
                    __half2 h2 = __floats2half2_rn(a[4] * inv, a[5] * inv);
                    __half2 h3 = __floats2half2_rn(a[6] * inv, a[7] * inv);
                    uint4* dst = (uint4*)&As[r][l16 * 4];
                    dst->x = *(uint32_t*)&h0; dst->y = *(uint32_t*)&h1;
                    dst->z = *(uint32_t*)&h2; dst->w = *(uint32_t*)&h3;
                }
            }
        }
    }
    CP_WAIT(0);
    __syncthreads();

    // ---- MMA over 4 K-chunks; A resident, B double-buffered ----
    float acc[2][NA][4];
#pragma unroll
    for (int m = 0; m < 2; m++)
#pragma unroll
        for (int n = 0; n < NA; n++)
#pragma unroll
            for (int j = 0; j < 4; j++) acc[m][n][j] = 0.f;

    for (int c = 0; c < 4; c++) {
        if (c < 3) {                                // prefetch next B chunk
            const int k0 = (c + 1) * 64;
            const int buf = (c + 1) & 1;
#pragma unroll
            for (int i = 0; i < OUT / 16; i++) {
                int idx = i * 128 + tid;
                int o = idx >> 3, q = idx & 7;
                cp16((uint32_t)__cvta_generic_to_shared(&Bs[buf][o][q * 4]),
                     Bw + (size_t)o * 256 + k0 + q * 8);
            }
            CP_COMMIT();
        }

        const int buf = c & 1;
        const int cbase = c * 32;
#pragma unroll
        for (int ks = 0; ks < 4; ks++) {
            const int offA = cbase + ks * 8;
            const int offB = ks * 8;
            uint32_t a[2][4];
#pragma unroll
            for (int m = 0; m < 2; m++) {
                int row = warp_m * 32 + m * 16 + g;
                a[m][0] = As[row][offA + t];
                a[m][1] = As[row + 8][offA + t];
                a[m][2] = As[row][offA + t + 4];
                a[m][3] = As[row + 8][offA + t + 4];
            }
            uint32_t b[NA][2];
#pragma unroll
            for (int n = 0; n < NA; n++) {
                int col = warp_n * (OUT / 2) + n * 8 + g;
                b[n][0] = Bs[buf][col][offB + t];
                b[n][1] = Bs[buf][col][offB + t + 4];
            }
#pragma unroll
            for (int m = 0; m < 2; m++)
#pragma unroll
                for (int n = 0; n < NA; n++)
                    mma_f16(acc[m][n], a[m], b[n]);
        }
        if (c < 3) {
            CP_WAIT(0);
            __syncthreads();
        }
    }

    // ---- epilogue ----
#pragma unroll
    for (int m = 0; m < 2; m++) {
        int r_lo = row0 + warp_m * 32 + m * 16 + g;
        int r_hi = r_lo + 8;
#pragma unroll
        for (int n = 0; n < NA; n++) {
            int col = warp_n * (OUT / 2) + n * 8 + t * 2;
            float bx = bias[col], by = bias[col + 1];
            float v0 = acc[m][n][0] + bx, v1 = acc[m][n][1] + by;
            float v2 = acc[m][n][2] + bx, v3 = acc[m][n][3] + by;
            if (RELU) {
                v0 = fmaxf(v0, 0.f); v1 = fmaxf(v1, 0.f);
                v2 = fmaxf(v2, 0.f); v3 = fmaxf(v3, 0.f);
            }
            if (HOUT) {
                uint16_t* C = (uint16_t*)Cout;
                __half2 lo = __floats2half2_rn(v0, v1);
                __half2 hi = __floats2half2_rn(v2, v3);
                if (r_lo < N_NODES) *(uint32_t*)(C + (size_t)r_lo * OUT + col) = *(uint32_t*)&lo;
                if (r_hi < N_NODES) *(uint32_t*)(C + (size_t)r_hi * OUT + col) = *(uint32_t*)&hi;
            } else {
                float* C = (float*)Cout;
                if (r_lo < N_NODES) *(float2*)(C + (size_t)r_lo * OUT + col) = make_float2(v0, v1);
                if (r_hi < N_NODES) *(float2*)(C + (size_t)r_hi * OUT + col) = make_float2(v2, v3);
            }
        }
    }
}

// ---------------- host launch ----------------
extern "C" void kernel_launch(void* const* d_in, const int* in_sizes, int n_in,
                              void* d_out, int out_size) {
    const float* x   = (const float*)d_in[0];
    const void*  ei  = d_in[1];
    const float* w1n = (const float*)d_in[2];
    const float* w1r = (const float*)d_in[3];
    const float* b1  = (const float*)d_in[4];
    const float* w2n = (const float*)d_in[5];
    const float* w2r = (const float*)d_in[6];
    const float* b2  = (const float*)d_in[7];
    const float* w3n = (const float*)d_in[8];
    const float* w3r = (const float*)d_in[9];
    const float* b3  = (const float*)d_in[10];

    int *ideg, *cnt;
    uint16_t *xh, *h1h, *h2h, *B1, *B2, *B3;
    cudaGetSymbolAddress((void**)&ideg, g_ideg);
    cudaGetSymbolAddress((void**)&cnt,  g_cnt);
    cudaGetSymbolAddress((void**)&xh,   g_xh);
    cudaGetSymbolAddress((void**)&h1h,  g_h1h);
    cudaGetSymbolAddress((void**)&h2h,  g_h2h);
    cudaGetSymbolAddress((void**)&B1,   g_B1);
    cudaGetSymbolAddress((void**)&B2,   g_B2);
    cudaGetSymbolAddress((void**)&B3,   g_B3);

    const int prepBlocks = (N_NODES * 64 + 81920 + 255) / 256;   // 12820
    const int layerGrid  = (N_NODES + 63) / 64;                  // 782

    // ---- structure + CSR + prep (3 kernels + 2 DMA memsets) ----
    cudaMemsetAsync(ideg, 0, 50048 * sizeof(int));
    cudaMemsetAsync(cnt,  0, 50048 * sizeof(int));
    convert_deg_prep<<<EDGE_BLOCKS + prepBlocks, 256>>>(ei, x, w1n, w1r, w2n, w2r, w3n, w3r);
    scan_local<<<196, 256>>>();
    scan_add_full<<<196, 256>>>();
    fill_csr<<<EDGE_BLOCKS, 256>>>();

    // ---- 3 fused layers (gather + GEMM in one kernel each) ----
    fused_layer<128, true,  true ><<<layerGrid, 128>>>(xh,  B1, b1, h1h);
    fused_layer<128, true,  true ><<<layerGrid, 128>>>(h1h, B2, b2, h2h);
    fused_layer<64,  false, false><<<layerGrid, 128>>>(h2h, B3, b3, d_out);
}

// round 12
// speedup vs baseline: 1.5950x; 1.5950x over previous
#include <cuda_runtime.h>
#include <cuda_fp16.h>
#include <cstdint>

#define N_NODES 50000
#define N_EDGES 600000
#define EDGE_BLOCKS 2344

// ---------------- scratch (static __device__, no allocations) ----------------
__device__ int      g_src[N_EDGES];
__device__ int      g_dst[N_EDGES];
__device__ int      g_csr[N_EDGES];
__device__ int      g_ideg[50048];
__device__ int      g_rowptr[N_NODES + 1];
__device__ int      g_bsum[256];
__device__ int      g_cnt[50048];                 // seeded with rowptr by scan_add_full
__device__ uint16_t g_aggh[(size_t)N_NODES * 128];
__device__ uint16_t g_xh  [(size_t)N_NODES * 128];
__device__ uint16_t g_h1h [(size_t)N_NODES * 128];
__device__ uint16_t g_h2h [(size_t)N_NODES * 128];
__device__ uint16_t g_B1[128 * 256];
__device__ uint16_t g_B2[128 * 256];
__device__ uint16_t g_B3[64 * 256];

// ---------------- mma / cp.async helpers ----------------
__device__ __forceinline__ void mma_f16(float* d, const uint32_t* a, const uint32_t* b) {
    asm volatile(
        "mma.sync.aligned.m16n8k16.row.col.f32.f16.f16.f32 "
        "{%0,%1,%2,%3}, {%4,%5,%6,%7}, {%8,%9}, {%0,%1,%2,%3};"
        : "+f"(d[0]), "+f"(d[1]), "+f"(d[2]), "+f"(d[3])
        : "r"(a[0]), "r"(a[1]), "r"(a[2]), "r"(a[3]), "r"(b[0]), "r"(b[1]));
}
__device__ __forceinline__ void cp16(uint32_t smem, const void* g) {
    asm volatile("cp.async.ca.shared.global [%0], [%1], 16;" :: "r"(smem), "l"(g));
}
#define CP_COMMIT() asm volatile("cp.async.commit_group;")
#define CP_WAIT(N)  asm volatile("cp.async.wait_group %0;" :: "n"(N))

// ---------------- structure: convert + degree (block-local dtype detect) + fp16 prep ----------------
__global__ void convert_deg_prep(const void* p, const float* __restrict__ x,
                                 const float* w1n, const float* w1r,
                                 const float* w2n, const float* w2r,
                                 const float* w3n, const float* w3r) {
    int b = blockIdx.x;
    if (b < EDGE_BLOCKS) {
        // block-local dtype sniff: int64 edge values < 50000 -> zero high words
        __shared__ int cnt_s;
        if (threadIdx.x == 0) cnt_s = 0;
        __syncthreads();
        const unsigned int* p32 = (const unsigned int*)p;
        int local = 0;
#pragma unroll
        for (int i = threadIdx.x; i < 2048; i += 256)
            if (p32[2 * i + 1] == 0u) local++;
#pragma unroll
        for (int o = 16; o > 0; o >>= 1) local += __shfl_down_sync(~0u, local, o);
        if ((threadIdx.x & 31) == 0) atomicAdd(&cnt_s, local);
        __syncthreads();
        bool is64 = (cnt_s > 1024);

        int e = b * 256 + threadIdx.x;
        if (e >= N_EDGES) return;
        int s, d;
        if (is64) {
            const long long* q = (const long long*)p;
            s = (int)q[e];
            d = (int)q[N_EDGES + e];
        } else {
            const int* q = (const int*)p;
            s = q[e];
            d = q[N_EDGES + e];
        }
        g_src[e] = s;
        g_dst[e] = d;
        atomicAdd(&g_ideg[d], 1);
        return;
    }
    int i = (b - EDGE_BLOCKS) * 256 + threadIdx.x;
    const int NX = N_NODES * 64;                  // half2 count for x
    if (i < NX) {
        float2 v = ((const float2*)x)[i];
        ((__half2*)g_xh)[i] = __floats2half2_rn(v.x, v.y);
        return;
    }
    int idx = i - NX;
    if (idx < 32768) {
        int o = idx >> 8, k = idx & 255;
        float v = (k < 128) ? w1n[o * 128 + k] : w1r[o * 128 + (k - 128)];
        g_B1[idx] = __half_as_ushort(__float2half_rn(v));
    } else if (idx < 65536) {
        int j = idx - 32768;
        int o = j >> 8, k = j & 255;
        float v = (k < 128) ? w2n[o * 128 + k] : w2r[o * 128 + (k - 128)];
        g_B2[j] = __half_as_ushort(__float2half_rn(v));
    } else if (idx < 81920) {
        int j = idx - 65536;
        int o = j >> 8, k = j & 255;
        float v = (k < 128) ? w3n[o * 128 + k] : w3r[o * 128 + (k - 128)];
        g_B3[j] = __half_as_ushort(__float2half_rn(v));
    }
}

// ---- scan phase 1: per-block exclusive scan of g_ideg, block sums to g_bsum ----
__global__ void scan_local() {            // grid 196, block 256
    __shared__ int wtot[8];
    int b = blockIdx.x, t = threadIdx.x, i = b * 256 + t;
    int lane = t & 31, wid = t >> 5;
    int v = (i < N_NODES) ? g_ideg[i] : 0;
    int x = v;
#pragma unroll
    for (int o = 1; o < 32; o <<= 1) {
        int y = __shfl_up_sync(~0u, x, o);
        if (lane >= o) x += y;
    }
    if (lane == 31) wtot[wid] = x;
    __syncthreads();
    if (wid == 0) {
        int w = (lane < 8) ? wtot[lane] : 0;
#pragma unroll
        for (int o = 1; o < 8; o <<= 1) {
            int y = __shfl_up_sync(0xffffffffu, w, o);
            if (lane >= o) w += y;
        }
        if (lane < 8) wtot[lane] = w;
    }
    __syncthreads();
    int excl = x - v + (wid > 0 ? wtot[wid - 1] : 0);
    if (i < N_NODES) g_rowptr[i] = excl;
    if (t == 255) g_bsum[b] = excl + v;
}

// ---- scan phase 2 (fused): redundant scan of block sums; writes rowptr AND seeds g_cnt ----
__global__ void scan_add_full() {         // grid 196, block 256
    __shared__ int sb[256];
    __shared__ int wtot[8];
    int t = threadIdx.x, lane = t & 31, wid = t >> 5;
    int v = (t < 196) ? g_bsum[t] : 0;
    int x = v;
#pragma unroll
    for (int o = 1; o < 32; o <<= 1) {
        int y = __shfl_up_sync(~0u, x, o);
        if (lane >= o) x += y;
    }
    if (lane == 31) wtot[wid] = x;
    __syncthreads();
    if (wid == 0) {
        int w = (lane < 8) ? wtot[lane] : 0;
#pragma unroll
        for (int o = 1; o < 8; o <<= 1) {
            int y = __shfl_up_sync(0xffffffffu, w, o);
            if (lane >= o) w += y;
        }
        if (lane < 8) wtot[lane] = w;
    }
    __syncthreads();
    sb[t] = x - v + (wid > 0 ? wtot[wid - 1] : 0);
    __syncthreads();
    int add = sb[blockIdx.x];
    int i = blockIdx.x * 256 + t;
    if (i < N_NODES) {
        int r = g_rowptr[i] + add;
        g_rowptr[i] = r;
        g_cnt[i]    = r;                   // seed fill cursor
    }
    if (blockIdx.x == 0 && t == 0) g_rowptr[N_NODES] = N_EDGES;
}

// ---- fill: cursor IS the rowptr copy; one atomic, one write per edge ----
__global__ void fill_csr() {
    int e = blockIdx.x * blockDim.x + threadIdx.x;
    if (e >= N_EDGES) return;
    int pos = atomicAdd(&g_cnt[g_dst[e]], 1);
    g_csr[pos] = g_src[e];
}

// ---------------- gather-mean: one warp per node, 2 half-warps, 4-deep MLP ----------------
__global__ void gather_mean(const uint16_t* __restrict__ Xh) {
    int w = (blockIdx.x * blockDim.x + threadIdx.x) >> 5;
    int lane = threadIdx.x & 31;
    if (w >= N_NODES) return;
    int beg = g_rowptr[w], end = g_rowptr[w + 1];
    int half = lane >> 4;
    int l16  = lane & 15;

    float a[8];
#pragma unroll
    for (int j = 0; j < 8; j++) a[j] = 0.f;

    int e = beg + half;
    for (; e + 6 < end; e += 8) {
        int s0 = g_csr[e],     s1 = g_csr[e + 2];
        int s2 = g_csr[e + 4], s3 = g_csr[e + 6];
        uint4 u0 = ((const uint4*)(Xh + (size_t)s0 * 128))[l16];
        uint4 u1 = ((const uint4*)(Xh + (size_t)s1 * 128))[l16];
        uint4 u2 = ((const uint4*)(Xh + (size_t)s2 * 128))[l16];
        uint4 u3 = ((const uint4*)(Xh + (size_t)s3 * 128))[l16];
        float2 f;
        f = __half22float2(*(__half2*)&u0.x); a[0] += f.x; a[1] += f.y;
        f = __half22float2(*(__half2*)&u0.y); a[2] += f.x; a[3] += f.y;
        f = __half22float2(*(__half2*)&u0.z); a[4] += f.x; a[5] += f.y;
        f = __half22float2(*(__half2*)&u0.w); a[6] += f.x; a[7] += f.y;
        f = __half22float2(*(__half2*)&u1.x); a[0] += f.x; a[1] += f.y;
        f = __half22float2(*(__half2*)&u1.y); a[2] += f.x; a[3] += f.y;
        f = __half22float2(*(__half2*)&u1.z); a[4] += f.x; a[5] += f.y;
        f = __half22float2(*(__half2*)&u1.w); a[6] += f.x; a[7] += f.y;
        f = __half22float2(*(__half2*)&u2.x); a[0] += f.x; a[1] += f.y;
        f = __half22float2(*(__half2*)&u2.y); a[2] += f.x; a[3] += f.y;
        f = __half22float2(*(__half2*)&u2.z); a[4] += f.x; a[5] += f.y;
        f = __half22float2(*(__half2*)&u2.w); a[6] += f.x; a[7] += f.y;
        f = __half22float2(*(__half2*)&u3.x); a[0] += f.x; a[1] += f.y;
        f = __half22float2(*(__half2*)&u3.y); a[2] += f.x; a[3] += f.y;
        f = __half22float2(*(__half2*)&u3.z); a[4] += f.x; a[5] += f.y;
        f = __half22float2(*(__half2*)&u3.w); a[6] += f.x; a[7] += f.y;
    }
    for (; e < end; e += 2) {
        int s = g_csr[e];
        uint4 u = ((const uint4*)(Xh + (size_t)s * 128))[l16];
        float2 f;
        f = __half22float2(*(__half2*)&u.x); a[0] += f.x; a[1] += f.y;
        f = __half22float2(*(__half2*)&u.y); a[2] += f.x; a[3] += f.y;
        f = __half22float2(*(__half2*)&u.z); a[4] += f.x; a[5] += f.y;
        f = __half22float2(*(__half2*)&u.w); a[6] += f.x; a[7] += f.y;
    }
#pragma unroll
    for (int j = 0; j < 8; j++) a[j] += __shfl_down_sync(~0u, a[j], 16);

    if (half == 0) {
        float inv = 1.0f / fmaxf((float)(end - beg), 1.0f);
        __half2 h0 = __floats2half2_rn(a[0] * inv, a[1] * inv);
        __half2 h1 = __floats2half2_rn(a[2] * inv, a[3] * inv);
        __half2 h2 = __floats2half2_rn(a[4] * inv, a[5] * inv);
        __half2 h3 = __floats2half2_rn(a[6] * inv, a[7] * inv);
        uint4 o;
        o.x = *(uint32_t*)&h0; o.y = *(uint32_t*)&h1;
        o.z = *(uint32_t*)&h2; o.w = *(uint32_t*)&h3;
        ((uint4*)(g_aggh + (size_t)w * 128))[l16] = o;
    }
}

// ---------------- persistent tensor-core combine (M-tile 64, 4 warps, cp.async db) ----------------
template <int OUT, bool RELU, bool HOUT>
__global__ void __launch_bounds__(128, 4) combine_mma(
    const uint16_t* __restrict__ Aagg,
    const uint16_t* __restrict__ Aroot,
    const uint16_t* __restrict__ Bw,
    const float* __restrict__ bias,
    void* __restrict__ Cout)
{
    constexpr int NA = OUT / 16;
    constexpr int NTILES = (N_NODES + 63) / 64;   // 782
    __shared__ uint32_t As[2][64][36];
    __shared__ uint32_t Bs[2][OUT][36];

    const int tid    = threadIdx.x;
    const int wid    = tid >> 5;
    const int lane   = tid & 31;
    const int warp_m = wid >> 1;
    const int warp_n = wid & 1;
    const int g      = lane >> 2;
    const int t      = lane & 3;

    for (int tile = blockIdx.x; tile < NTILES; tile += gridDim.x) {
        const int row0 = tile * 64;

        float acc[2][NA][4];
#pragma unroll
        for (int m = 0; m < 2; m++)
#pragma unroll
            for (int n = 0; n < NA; n++)
#pragma unroll
                for (int j = 0; j < 4; j++) acc[m][n][j] = 0.f;

        auto issue = [&](int c, int buf) {
            const int k0 = c * 64;
            const uint16_t* src = (k0 < 128) ? (Aagg + k0) : (Aroot + (k0 - 128));
#pragma unroll
            for (int i = 0; i < 4; i++) {
                int idx = i * 128 + tid;
                int r = idx >> 3, q = idx & 7;
                int grow = row0 + r;
                if (grow > N_NODES - 1) grow = N_NODES - 1;
                cp16((uint32_t)__cvta_generic_to_shared(&As[buf][r][q * 4]),
                     src + (size_t)grow * 128 + q * 8);
            }
#pragma unroll
            for (int i = 0; i < OUT / 16; i++) {
                int idx = i * 128 + tid;
                int o = idx >> 3, q = idx & 7;
                cp16((uint32_t)__cvta_generic_to_shared(&Bs[buf][o][q * 4]),
                     Bw + (size_t)o * 256 + k0 + q * 8);
            }
            CP_COMMIT();
        };

        issue(0, 0);

        for (int c = 0; c < 4; c++) {
            if (c < 3) { issue(c + 1, (c + 1) & 1); CP_WAIT(1); }
            else       { CP_WAIT(0); }
            __syncthreads();

            const int buf = c & 1;
#pragma unroll
            for (int ks = 0; ks < 4; ks++) {
                const int off = ks * 8;
                uint32_t a[2][4];
#pragma unroll
                for (int m = 0; m < 2; m++) {
                    int row = warp_m * 32 + m * 16 + g;
                    a[m][0] = As[buf][row][off + t];
                    a[m][1] = As[buf][row + 8][off + t];
                    a[m][2] = As[buf][row][off + t + 4];
                    a[m][3] = As[buf][row + 8][off + t + 4];
                }
                uint32_t b[NA][2];
#pragma unroll
                for (int n = 0; n < NA; n++) {
                    int col = warp_n * (OUT / 2) + n * 8 + g;
                    b[n][0] = Bs[buf][col][off + t];
                    b[n][1] = Bs[buf][col][off + t + 4];
                }
#pragma unroll
                for (int m = 0; m < 2; m++)
#pragma unroll
                    for (int n = 0; n < NA; n++)
                        mma_f16(acc[m][n], a[m], b[n]);
            }
            __syncthreads();
        }

        // ---- epilogue ----
#pragma unroll
        for (int m = 0; m < 2; m++) {
            int r_lo = row0 + warp_m * 32 + m * 16 + g;
            int r_hi = r_lo + 8;
#pragma unroll
            for (int n = 0; n < NA; n++) {
                int col = warp_n * (OUT / 2) + n * 8 + t * 2;
                float bx = bias[col], by = bias[col + 1];
                float v0 = acc[m][n][0] + bx, v1 = acc[m][n][1] + by;
                float v2 = acc[m][n][2] + bx, v3 = acc[m][n][3] + by;
                if (RELU) {
                    v0 = fmaxf(v0, 0.f); v1 = fmaxf(v1, 0.f);
                    v2 = fmaxf(v2, 0.f); v3 = fmaxf(v3, 0.f);
                }
                if (HOUT) {
                    uint16_t* C = (uint16_t*)Cout;
                    __half2 lo = __floats2half2_rn(v0, v1);
                    __half2 hi = __floats2half2_rn(v2, v3);
                    if (r_lo < N_NODES) *(uint32_t*)(C + (size_t)r_lo * OUT + col) = *(uint32_t*)&lo;
                    if (r_hi < N_NODES) *(uint32_t*)(C + (size_t)r_hi * OUT + col) = *(uint32_t*)&hi;
                } else {
                    float* C = (float*)Cout;
                    if (r_lo < N_NODES) *(float2*)(C + (size_t)r_lo * OUT + col) = make_float2(v0, v1);
                    if (r_hi < N_NODES) *(float2*)(C + (size_t)r_hi * OUT + col) = make_float2(v2, v3);
                }
            }
        }
    }
}

// ---------------- host launch ----------------
extern "C" void kernel_launch(void* const* d_in, const int* in_sizes, int n_in,
                              void* d_out, int out_size) {
    const float* x   = (const float*)d_in[0];
    const void*  ei  = d_in[1];
    const float* w1n = (const float*)d_in[2];
    const float* w1r = (const float*)d_in[3];
    const float* b1  = (const float*)d_in[4];
    const float* w2n = (const float*)d_in[5];
    const float* w2r = (const float*)d_in[6];
    const float* b2  = (const float*)d_in[7];
    const float* w3n = (const float*)d_in[8];
    const float* w3r = (const float*)d_in[9];
    const float* b3  = (const float*)d_in[10];

    int* ideg;
    uint16_t *xh, *aggh, *h1h, *h2h, *B1, *B2, *B3;
    cudaGetSymbolAddress((void**)&ideg, g_ideg);
    cudaGetSymbolAddress((void**)&xh,   g_xh);
    cudaGetSymbolAddress((void**)&aggh, g_aggh);
    cudaGetSymbolAddress((void**)&h1h,  g_h1h);
    cudaGetSymbolAddress((void**)&h2h,  g_h2h);
    cudaGetSymbolAddress((void**)&B1,   g_B1);
    cudaGetSymbolAddress((void**)&B2,   g_B2);
    cudaGetSymbolAddress((void**)&B3,   g_B3);

    const int TPB = 256;
    const int gatherBlocks = (N_NODES * 32 + TPB - 1) / TPB;              // 6250
    const int prepBlocks   = (N_NODES * 64 + 81920 + TPB - 1) / TPB;      // 12820
    const int gemm128Grid  = 592;
    const int gemm64Grid   = 782;

    // ---- structure + CSR + prep ----
    cudaMemsetAsync(ideg, 0, 50048 * sizeof(int));
    convert_deg_prep<<<EDGE_BLOCKS + prepBlocks, TPB>>>(ei, x, w1n, w1r, w2n, w2r, w3n, w3r);
    scan_local<<<196, 256>>>();
    scan_add_full<<<196, 256>>>();
    fill_csr<<<EDGE_BLOCKS, TPB>>>();

    // ---- layer 1 ----
    gather_mean<<<gatherBlocks, TPB>>>(xh);
    combine_mma<128, true, true><<<gemm128Grid, 128>>>(aggh, xh, B1, b1, h1h);

    // ---- layer 2 ----
    gather_mean<<<gatherBlocks, TPB>>>(h1h);
    combine_mma<128, true, true><<<gemm128Grid, 128>>>(aggh, h1h, B2, b2, h2h);

    // ---- layer 3 ----
    gather_mean<<<gatherBlocks, TPB>>>(h2h);
    combine_mma<64, false, false><<<gemm64Grid, 128>>>(aggh, h2h, B3, b3, d_out);
}

// round 13
// speedup vs baseline: 1.6191x; 1.0151x over previous
#include <cuda_runtime.h>
#include <cuda_fp16.h>
#include <cstdint>

#define N_NODES 50000
#define N_EDGES 600000
#define EDGE_BLOCKS 2344

// ---------------- scratch (static __device__, no allocations) ----------------
__device__ int      g_csr[N_EDGES];
__device__ int      g_ideg[50048];
__device__ int      g_rowptr[N_NODES + 1];
__device__ int      g_bsum[256];
__device__ int      g_cnt[50048];                 // seeded with rowptr by scan_add_full
__device__ uint16_t g_aggh[(size_t)N_NODES * 128];
__device__ uint16_t g_xh  [(size_t)N_NODES * 128];
__device__ uint16_t g_h1h [(size_t)N_NODES * 128];
__device__ uint16_t g_h2h [(size_t)N_NODES * 128];
__device__ uint16_t g_B1[128 * 256];
__device__ uint16_t g_B2[128 * 256];
__device__ uint16_t g_B3[64 * 256];

// ---------------- mma / cp.async helpers ----------------
__device__ __forceinline__ void mma_f16(float* d, const uint32_t* a, const uint32_t* b) {
    asm volatile(
        "mma.sync.aligned.m16n8k16.row.col.f32.f16.f16.f32 "
        "{%0,%1,%2,%3}, {%4,%5,%6,%7}, {%8,%9}, {%0,%1,%2,%3};"
        : "+f"(d[0]), "+f"(d[1]), "+f"(d[2]), "+f"(d[3])
        : "r"(a[0]), "r"(a[1]), "r"(a[2]), "r"(a[3]), "r"(b[0]), "r"(b[1]));
}
__device__ __forceinline__ void cp16(uint32_t smem, const void* g) {
    asm volatile("cp.async.ca.shared.global [%0], [%1], 16;" :: "r"(smem), "l"(g));
}
#define CP_COMMIT() asm volatile("cp.async.commit_group;")
#define CP_WAIT(N)  asm volatile("cp.async.wait_group %0;" :: "n"(N))

// ---- dtype sniff: int64 LE edge indices (< 50000) have ALL odd 32-bit words zero.
// 16 broadcast samples -> false-positive prob (1/50000)^16 ~ 0. L1-hot, no sync.
__device__ __forceinline__ bool sniff_is64(const unsigned int* p32) {
    bool is64 = true;
#pragma unroll
    for (int j = 1; j < 32; j += 2) is64 &= (p32[j] == 0u);
    return is64;
}
__device__ __forceinline__ void load_edge(const void* p, bool is64, int e, int& s, int& d) {
    if (is64) {
        const long long* q = (const long long*)p;
        s = (int)q[e];
        d = (int)q[N_EDGES + e];
    } else {
        const int* q = (const int*)p;
        s = q[e];
        d = q[N_EDGES + e];
    }
}

// ---------------- structure: degree histogram + fp16 prep (one kernel) ----------------
__global__ void deg_prep(const void* p, const float* __restrict__ x,
                         const float* w1n, const float* w1r,
                         const float* w2n, const float* w2r,
                         const float* w3n, const float* w3r) {
    int b = blockIdx.x;
    if (b < EDGE_BLOCKS) {
        bool is64 = sniff_is64((const unsigned int*)p);
        int e = b * 256 + threadIdx.x;
        if (e >= N_EDGES) return;
        int s, d;
        load_edge(p, is64, e, s, d);
        atomicAdd(&g_ideg[d], 1);
        return;
    }
    int i = (b - EDGE_BLOCKS) * 256 + threadIdx.x;
    const int NX = N_NODES * 64;                  // half2 count for x
    if (i < NX) {
        float2 v = ((const float2*)x)[i];
        ((__half2*)g_xh)[i] = __floats2half2_rn(v.x, v.y);
        return;
    }
    int idx = i - NX;
    if (idx < 32768) {
        int o = idx >> 8, k = idx & 255;
        float v = (k < 128) ? w1n[o * 128 + k] : w1r[o * 128 + (k - 128)];
        g_B1[idx] = __half_as_ushort(__float2half_rn(v));
    } else if (idx < 65536) {
        int j = idx - 32768;
        int o = j >> 8, k = j & 255;
        float v = (k < 128) ? w2n[o * 128 + k] : w2r[o * 128 + (k - 128)];
        g_B2[j] = __half_as_ushort(__float2half_rn(v));
    } else if (idx < 81920) {
        int j = idx - 65536;
        int o = j >> 8, k = j & 255;
        float v = (k < 128) ? w3n[o * 128 + k] : w3r[o * 128 + (k - 128)];
        g_B3[j] = __half_as_ushort(__float2half_rn(v));
    }
}

// ---- scan phase 1: per-block exclusive scan of g_ideg, block sums to g_bsum ----
__global__ void scan_local() {            // grid 196, block 256
    __shared__ int wtot[8];
    int b = blockIdx.x, t = threadIdx.x, i = b * 256 + t;
    int lane = t & 31, wid = t >> 5;
    int v = (i < N_NODES) ? g_ideg[i] : 0;
    int x = v;
#pragma unroll
    for (int o = 1; o < 32; o <<= 1) {
        int y = __shfl_up_sync(~0u, x, o);
        if (lane >= o) x += y;
    }
    if (lane == 31) wtot[wid] = x;
    __syncthreads();
    if (wid == 0) {
        int w = (lane < 8) ? wtot[lane] : 0;
#pragma unroll
        for (int o = 1; o < 8; o <<= 1) {
            int y = __shfl_up_sync(0xffffffffu, w, o);
            if (lane >= o) w += y;
        }
        if (lane < 8) wtot[lane] = w;
    }
    __syncthreads();
    int excl = x - v + (wid > 0 ? wtot[wid - 1] : 0);
    if (i < N_NODES) g_rowptr[i] = excl;
    if (t == 255) g_bsum[b] = excl + v;
}

// ---- scan phase 2 (fused): redundant scan of block sums; writes rowptr AND seeds g_cnt ----
__global__ void scan_add_full() {         // grid 196, block 256
    __shared__ int sb[256];
    __shared__ int wtot[8];
    int t = threadIdx.x, lane = t & 31, wid = t >> 5;
    int v = (t < 196) ? g_bsum[t] : 0;
    int x = v;
#pragma unroll
    for (int o = 1; o < 32; o <<= 1) {
        int y = __shfl_up_sync(~0u, x, o);
        if (lane >= o) x += y;
    }
    if (lane == 31) wtot[wid] = x;
    __syncthreads();
    if (wid == 0) {
        int w = (lane < 8) ? wtot[lane] : 0;
#pragma unroll
        for (int o = 1; o < 8; o <<= 1) {
            int y = __shfl_up_sync(0xffffffffu, w, o);
            if (lane >= o) w += y;
        }
        if (lane < 8) wtot[lane] = w;
    }
    __syncthreads();
    sb[t] = x - v + (wid > 0 ? wtot[wid - 1] : 0);
    __syncthreads();
    int add = sb[blockIdx.x];
    int i = blockIdx.x * 256 + t;
    if (i < N_NODES) {
        int r = g_rowptr[i] + add;
        g_rowptr[i] = r;
        g_cnt[i]    = r;                   // seed fill cursor
    }
    if (blockIdx.x == 0 && t == 0) g_rowptr[N_NODES] = N_EDGES;
}

// ---- fill: reads edge_index directly; one atomic + one write per edge ----
__global__ void fill_csr(const void* p) {
    bool is64 = sniff_is64((const unsigned int*)p);
    int e = blockIdx.x * blockDim.x + threadIdx.x;
    if (e >= N_EDGES) return;
    int s, d;
    load_edge(p, is64, e, s, d);
    int pos = atomicAdd(&g_cnt[d], 1);
    g_csr[pos] = s;
}

// ---------------- gather-mean: one warp per node, 2 half-warps, 4-deep MLP ----------------
__global__ void gather_mean(const uint16_t* __restrict__ Xh) {
    int w = (blockIdx.x * blockDim.x + threadIdx.x) >> 5;
    int lane = threadIdx.x & 31;
    if (w >= N_NODES) return;
    int beg = g_rowptr[w], end = g_rowptr[w + 1];
    int half = lane >> 4;
    int l16  = lane & 15;

    float a[8];
#pragma unroll
    for (int j = 0; j < 8; j++) a[j] = 0.f;

    int e = beg + half;
    for (; e + 6 < end; e += 8) {
        int s0 = g_csr[e],     s1 = g_csr[e + 2];
        int s2 = g_csr[e + 4], s3 = g_csr[e + 6];
        uint4 u0 = ((const uint4*)(Xh + (size_t)s0 * 128))[l16];
        uint4 u1 = ((const uint4*)(Xh + (size_t)s1 * 128))[l16];
        uint4 u2 = ((const uint4*)(Xh + (size_t)s2 * 128))[l16];
        uint4 u3 = ((const uint4*)(Xh + (size_t)s3 * 128))[l16];
        float2 f;
        f = __half22float2(*(__half2*)&u0.x); a[0] += f.x; a[1] += f.y;
        f = __half22float2(*(__half2*)&u0.y); a[2] += f.x; a[3] += f.y;
        f = __half22float2(*(__half2*)&u0.z); a[4] += f.x; a[5] += f.y;
        f = __half22float2(*(__half2*)&u0.w); a[6] += f.x; a[7] += f.y;
        f = __half22float2(*(__half2*)&u1.x); a[0] += f.x; a[1] += f.y;
        f = __half22float2(*(__half2*)&u1.y); a[2] += f.x; a[3] += f.y;
        f = __half22float2(*(__half2*)&u1.z); a[4] += f.x; a[5] += f.y;
        f = __half22float2(*(__half2*)&u1.w); a[6] += f.x; a[7] += f.y;
        f = __half22float2(*(__half2*)&u2.x); a[0] += f.x; a[1] += f.y;
        f = __half22float2(*(__half2*)&u2.y); a[2] += f.x; a[3] += f.y;
        f = __half22float2(*(__half2*)&u2.z); a[4] += f.x; a[5] += f.y;
        f = __half22float2(*(__half2*)&u2.w); a[6] += f.x; a[7] += f.y;
        f = __half22float2(*(__half2*)&u3.x); a[0] += f.x; a[1] += f.y;
        f = __half22float2(*(__half2*)&u3.y); a[2] += f.x; a[3] += f.y;
        f = __half22float2(*(__half2*)&u3.z); a[4] += f.x; a[5] += f.y;
        f = __half22float2(*(__half2*)&u3.w); a[6] += f.x; a[7] += f.y;
    }
    for (; e < end; e += 2) {
        int s = g_csr[e];
        uint4 u = ((const uint4*)(Xh + (size_t)s * 128))[l16];
        float2 f;
        f = __half22float2(*(__half2*)&u.x); a[0] += f.x; a[1] += f.y;
        f = __half22float2(*(__half2*)&u.y); a[2] += f.x; a[3] += f.y;
        f = __half22float2(*(__half2*)&u.z); a[4] += f.x; a[5] += f.y;
        f = __half22float2(*(__half2*)&u.w); a[6] += f.x; a[7] += f.y;
    }
#pragma unroll
    for (int j = 0; j < 8; j++) a[j] += __shfl_down_sync(~0u, a[j], 16);

    if (half == 0) {
        float inv = 1.0f / fmaxf((float)(end - beg), 1.0f);
        __half2 h0 = __floats2half2_rn(a[0] * inv, a[1] * inv);
        __half2 h1 = __floats2half2_rn(a[2] * inv, a[3] * inv);
        __half2 h2 = __floats2half2_rn(a[4] * inv, a[5] * inv);
        __half2 h3 = __floats2half2_rn(a[6] * inv, a[7] * inv);
        uint4 o;
        o.x = *(uint32_t*)&h0; o.y = *(uint32_t*)&h1;
        o.z = *(uint32_t*)&h2; o.w = *(uint32_t*)&h3;
        ((uint4*)(g_aggh + (size_t)w * 128))[l16] = o;
    }
}

// ---------------- persistent tensor-core combine (M-tile 64, 4 warps, cp.async db) ----------------
template <int OUT, bool RELU, bool HOUT>
__global__ void __launch_bounds__(128, 4) combine_mma(
    const uint16_t* __restrict__ Aagg,
    const uint16_t* __restrict__ Aroot,
    const uint16_t* __restrict__ Bw,
    const float* __restrict__ bias,
    void* __restrict__ Cout)
{
    constexpr int NA = OUT / 16;
    constexpr int NTILES = (N_NODES + 63) / 64;   // 782
    __shared__ uint32_t As[2][64][36];
    __shared__ uint32_t Bs[2][OUT][36];

    const int tid    = threadIdx.x;
    const int wid    = tid >> 5;
    const int lane   = tid & 31;
    const int warp_m = wid >> 1;
    const int warp_n = wid & 1;
    const int g      = lane >> 2;
    const int t      = lane & 3;

    for (int tile = blockIdx.x; tile < NTILES; tile += gridDim.x) {
        const int row0 = tile * 64;

        float acc[2][NA][4];
#pragma unroll
        for (int m = 0; m < 2; m++)
#pragma unroll
            for (int n = 0; n < NA; n++)
#pragma unroll
                for (int j = 0; j < 4; j++) acc[m][n][j] = 0.f;

        auto issue = [&](int c, int buf) {
            const int k0 = c * 64;
            const uint16_t* src = (k0 < 128) ? (Aagg + k0) : (Aroot + (k0 - 128));
#pragma unroll
            for (int i = 0; i < 4; i++) {
                int idx = i * 128 + tid;
                int r = idx >> 3, q = idx & 7;
                int grow = row0 + r;
                if (grow > N_NODES - 1) grow = N_NODES - 1;
                cp16((uint32_t)__cvta_generic_to_shared(&As[buf][r][q * 4]),
                     src + (size_t)grow * 128 + q * 8);
            }
#pragma unroll
            for (int i = 0; i < OUT / 16; i++) {
                int idx = i * 128 + tid;
                int o = idx >> 3, q = idx & 7;
                cp16((uint32_t)__cvta_generic_to_shared(&Bs[buf][o][q * 4]),
                     Bw + (size_t)o * 256 + k0 + q * 8);
            }
            CP_COMMIT();
        };

        issue(0, 0);

        for (int c = 0; c < 4; c++) {
            if (c < 3) { issue(c + 1, (c + 1) & 1); CP_WAIT(1); }
            else       { CP_WAIT(0); }
            __syncthreads();

            const int buf = c & 1;
#pragma unroll
            for (int ks = 0; ks < 4; ks++) {
                const int off = ks * 8;
                uint32_t a[2][4];
#pragma unroll
                for (int m = 0; m < 2; m++) {
                    int row = warp_m * 32 + m * 16 + g;
                    a[m][0] = As[buf][row][off + t];
                    a[m][1] = As[buf][row + 8][off + t];
                    a[m][2] = As[buf][row][off + t + 4];
                    a[m][3] = As[buf][row + 8][off + t + 4];
                }
                uint32_t b[NA][2];
#pragma unroll
                for (int n = 0; n < NA; n++) {
                    int col = warp_n * (OUT / 2) + n * 8 + g;
                    b[n][0] = Bs[buf][col][off + t];
                    b[n][1] = Bs[buf][col][off + t + 4];
                }
#pragma unroll
                for (int m = 0; m < 2; m++)
#pragma unroll
                    for (int n = 0; n < NA; n++)
                        mma_f16(acc[m][n], a[m], b[n]);
            }
            __syncthreads();
        }

        // ---- epilogue ----
#pragma unroll
        for (int m = 0; m < 2; m++) {
            int r_lo = row0 + warp_m * 32 + m * 16 + g;
            int r_hi = r_lo + 8;
#pragma unroll
            for (int n = 0; n < NA; n++) {
                int col = warp_n * (OUT / 2) + n * 8 + t * 2;
                float bx = bias[col], by = bias[col + 1];
                float v0 = acc[m][n][0] + bx, v1 = acc[m][n][1] + by;
                float v2 = acc[m][n][2] + bx, v3 = acc[m][n][3] + by;
                if (RELU) {
                    v0 = fmaxf(v0, 0.f); v1 = fmaxf(v1, 0.f);
                    v2 = fmaxf(v2, 0.f); v3 = fmaxf(v3, 0.f);
                }
                if (HOUT) {
                    uint16_t* C = (uint16_t*)Cout;
                    __half2 lo = __floats2half2_rn(v0, v1);
                    __half2 hi = __floats2half2_rn(v2, v3);
                    if (r_lo < N_NODES) *(uint32_t*)(C + (size_t)r_lo * OUT + col) = *(uint32_t*)&lo;
                    if (r_hi < N_NODES) *(uint32_t*)(C + (size_t)r_hi * OUT + col) = *(uint32_t*)&hi;
                } else {
                    float* C = (float*)Cout;
                    if (r_lo < N_NODES) *(float2*)(C + (size_t)r_lo * OUT + col) = make_float2(v0, v1);
                    if (r_hi < N_NODES) *(float2*)(C + (size_t)r_hi * OUT + col) = make_float2(v2, v3);
                }
            }
        }
    }
}

// ---------------- host launch ----------------
extern "C" void kernel_launch(void* const* d_in, const int* in_sizes, int n_in,
                              void* d_out, int out_size) {
    const float* x   = (const float*)d_in[0];
    const void*  ei  = d_in[1];
    const float* w1n = (const float*)d_in[2];
    const float* w1r = (const float*)d_in[3];
    const float* b1  = (const float*)d_in[4];
    const float* w2n = (const float*)d_in[5];
    const float* w2r = (const float*)d_in[6];
    const float* b2  = (const float*)d_in[7];
    const float* w3n = (const float*)d_in[8];
    const float* w3r = (const float*)d_in[9];
    const float* b3  = (const float*)d_in[10];

    int* ideg;
    uint16_t *xh, *aggh, *h1h, *h2h, *B1, *B2, *B3;
    cudaGetSymbolAddress((void**)&ideg, g_ideg);
    cudaGetSymbolAddress((void**)&xh,   g_xh);
    cudaGetSymbolAddress((void**)&aggh, g_aggh);
    cudaGetSymbolAddress((void**)&h1h,  g_h1h);
    cudaGetSymbolAddress((void**)&h2h,  g_h2h);
    cudaGetSymbolAddress((void**)&B1,   g_B1);
    cudaGetSymbolAddress((void**)&B2,   g_B2);
    cudaGetSymbolAddress((void**)&B3,   g_B3);

    const int TPB = 256;
    const int gatherBlocks = (N_NODES * 32 + TPB - 1) / TPB;              // 6250
    const int prepBlocks   = (N_NODES * 64 + 81920 + TPB - 1) / TPB;      // 12820
    const int gemm128Grid  = 592;
    const int gemm64Grid   = 782;

    // ---- structure + CSR + prep ----
    cudaMemsetAsync(ideg, 0, 50048 * sizeof(int));
    deg_prep<<<EDGE_BLOCKS + prepBlocks, TPB>>>(ei, x, w1n, w1r, w2n, w2r, w3n, w3r);
    scan_local<<<196, 256>>>();
    scan_add_full<<<196, 256>>>();
    fill_csr<<<EDGE_BLOCKS, TPB>>>(ei);

    // ---- layer 1 ----
    gather_mean<<<gatherBlocks, TPB>>>(xh);
    combine_mma<128, true, true><<<gemm128Grid, 128>>>(aggh, xh, B1, b1, h1h);

    // ---- layer 2 ----
    gather_mean<<<gatherBlocks, TPB>>>(h1h);
    combine_mma<128, true, true><<<gemm128Grid, 128>>>(aggh, h1h, B2, b2, h2h);

    // ---- layer 3 ----
    gather_mean<<<gatherBlocks, TPB>>>(h2h);
    combine_mma<64, false, false><<<gemm64Grid, 128>>>(aggh, h2h, B3, b3, d_out);
}

// round 14
// speedup vs baseline: 1.6448x; 1.0159x over previous
#include <cuda_runtime.h>
#include <cuda_fp16.h>
#include <cstdint>

#define N_NODES 50000
#define N_EDGES 600000
#define EDGE_BLOCKS4 586          // ceil(600000 / 1024), 4 edges per thread

// ---------------- scratch (static __device__, no allocations) ----------------
__device__ int      g_csr[N_EDGES];
__device__ int      g_ideg[50048];
__device__ int      g_rowptr[N_NODES + 1];
__device__ int      g_bsum[256];
__device__ int      g_cnt[50048];                 // seeded with rowptr by scan_add_full
__device__ uint16_t g_aggh[(size_t)N_NODES * 128];
__device__ uint16_t g_xh  [(size_t)N_NODES * 128];
__device__ uint16_t g_h1h [(size_t)N_NODES * 128];
__device__ uint16_t g_h2h [(size_t)N_NODES * 128];
__device__ uint16_t g_B1[128 * 256];
__device__ uint16_t g_B2[128 * 256];
__device__ uint16_t g_B3[64 * 256];

// ---------------- mma / cp.async helpers ----------------
__device__ __forceinline__ void mma_f16(float* d, const uint32_t* a, const uint32_t* b) {
    asm volatile(
        "mma.sync.aligned.m16n8k16.row.col.f32.f16.f16.f32 "
        "{%0,%1,%2,%3}, {%4,%5,%6,%7}, {%8,%9}, {%0,%1,%2,%3};"
        : "+f"(d[0]), "+f"(d[1]), "+f"(d[2]), "+f"(d[3])
        : "r"(a[0]), "r"(a[1]), "r"(a[2]), "r"(a[3]), "r"(b[0]), "r"(b[1]));
}
__device__ __forceinline__ void cp16(uint32_t smem, const void* g) {
    asm volatile("cp.async.ca.shared.global [%0], [%1], 16;" :: "r"(smem), "l"(g));
}
#define CP_COMMIT() asm volatile("cp.async.commit_group;")
#define CP_WAIT(N)  asm volatile("cp.async.wait_group %0;" :: "n"(N))

// ---- dtype sniff: int64 LE edge indices (< 50000) have ALL odd 32-bit words zero.
__device__ __forceinline__ bool sniff_is64(const unsigned int* p32) {
    bool is64 = true;
#pragma unroll
    for (int j = 1; j < 32; j += 2) is64 &= (p32[j] == 0u);
    return is64;
}
__device__ __forceinline__ void load_edge(const void* p, bool is64, int e, int& s, int& d) {
    if (is64) {
        const long long* q = (const long long*)p;
        s = (int)q[e];
        d = (int)q[N_EDGES + e];
    } else {
        const int* q = (const int*)p;
        s = q[e];
        d = q[N_EDGES + e];
    }
}

// ---------------- structure: degree histogram (4 edges/thread) + fp16 prep ----------------
__global__ void deg_prep(const void* p, const float* __restrict__ x,
                         const float* w1n, const float* w1r,
                         const float* w2n, const float* w2r,
                         const float* w3n, const float* w3r) {
    int b = blockIdx.x;
    if (b < EDGE_BLOCKS4) {
        bool is64 = sniff_is64((const unsigned int*)p);
        int base = b * 1024 + threadIdx.x;
        int d[4];
#pragma unroll
        for (int k = 0; k < 4; k++) {
            int e = base + k * 256;
            if (e < N_EDGES) {
                int s;
                load_edge(p, is64, e, s, d[k]);
            } else d[k] = -1;
        }
#pragma unroll
        for (int k = 0; k < 4; k++)
            if (d[k] >= 0) atomicAdd(&g_ideg[d[k]], 1);
        return;
    }
    int i = (b - EDGE_BLOCKS4) * 256 + threadIdx.x;
    const int NX = N_NODES * 64;                  // half2 count for x
    if (i < NX) {
        float2 v = ((const float2*)x)[i];
        ((__half2*)g_xh)[i] = __floats2half2_rn(v.x, v.y);
        return;
    }
    int idx = i - NX;
    if (idx < 32768) {
        int o = idx >> 8, k = idx & 255;
        float v = (k < 128) ? w1n[o * 128 + k] : w1r[o * 128 + (k - 128)];
        g_B1[idx] = __half_as_ushort(__float2half_rn(v));
    } else if (idx < 65536) {
        int j = idx - 32768;
        int o = j >> 8, k = j & 255;
        float v = (k < 128) ? w2n[o * 128 + k] : w2r[o * 128 + (k - 128)];
        g_B2[j] = __half_as_ushort(__float2half_rn(v));
    } else if (idx < 81920) {
        int j = idx - 65536;
        int o = j >> 8, k = j & 255;
        float v = (k < 128) ? w3n[o * 128 + k] : w3r[o * 128 + (k - 128)];
        g_B3[j] = __half_as_ushort(__float2half_rn(v));
    }
}

// ---- scan phase 1: per-block exclusive scan of g_ideg, block sums to g_bsum ----
__global__ void scan_local() {            // grid 196, block 256
    __shared__ int wtot[8];
    int b = blockIdx.x, t = threadIdx.x, i = b * 256 + t;
    int lane = t & 31, wid = t >> 5;
    int v = (i < N_NODES) ? g_ideg[i] : 0;
    int x = v;
#pragma unroll
    for (int o = 1; o < 32; o <<= 1) {
        int y = __shfl_up_sync(~0u, x, o);
        if (lane >= o) x += y;
    }
    if (lane == 31) wtot[wid] = x;
    __syncthreads();
    if (wid == 0) {
        int w = (lane < 8) ? wtot[lane] : 0;
#pragma unroll
        for (int o = 1; o < 8; o <<= 1) {
            int y = __shfl_up_sync(0xffffffffu, w, o);
            if (lane >= o) w += y;
        }
        if (lane < 8) wtot[lane] = w;
    }
    __syncthreads();
    int excl = x - v + (wid > 0 ? wtot[wid - 1] : 0);
    if (i < N_NODES) g_rowptr[i] = excl;
    if (t == 255) g_bsum[b] = excl + v;
}

// ---- scan phase 2 (fused): redundant scan of block sums; writes rowptr AND seeds g_cnt ----
__global__ void scan_add_full() {         // grid 196, block 256
    __shared__ int sb[256];
    __shared__ int wtot[8];
    int t = threadIdx.x, lane = t & 31, wid = t >> 5;
    int v = (t < 196) ? g_bsum[t] : 0;
    int x = v;
#pragma unroll
    for (int o = 1; o < 32; o <<= 1) {
        int y = __shfl_up_sync(~0u, x, o);
        if (lane >= o) x += y;
    }
    if (lane == 31) wtot[wid] = x;
    __syncthreads();
    if (wid == 0) {
        int w = (lane < 8) ? wtot[lane] : 0;
#pragma unroll
        for (int o = 1; o < 8; o <<= 1) {
            int y = __shfl_up_sync(0xffffffffu, w, o);
            if (lane >= o) w += y;
        }
        if (lane < 8) wtot[lane] = w;
    }
    __syncthreads();
    sb[t] = x - v + (wid > 0 ? wtot[wid - 1] : 0);
    __syncthreads();
    int add = sb[blockIdx.x];
    int i = blockIdx.x * 256 + t;
    if (i < N_NODES) {
        int r = g_rowptr[i] + add;
        g_rowptr[i] = r;
        g_cnt[i]    = r;                   // seed fill cursor
    }
    if (blockIdx.x == 0 && t == 0) g_rowptr[N_NODES] = N_EDGES;
}

// ---- fill: 4 edges per thread, loads batched ahead of atomics ----
__global__ void fill_csr(const void* p) {
    bool is64 = sniff_is64((const unsigned int*)p);
    int base = blockIdx.x * 1024 + threadIdx.x;
    int s[4], d[4];
#pragma unroll
    for (int k = 0; k < 4; k++) {
        int e = base + k * 256;
        if (e < N_EDGES) load_edge(p, is64, e, s[k], d[k]);
        else d[k] = -1;
    }
#pragma unroll
    for (int k = 0; k < 4; k++) {
        if (d[k] >= 0) {
            int pos = atomicAdd(&g_cnt[d[k]], 1);
            g_csr[pos] = s[k];
        }
    }
}

// ---------------- gather-mean: one warp per node, 2 half-warps, 4-deep MLP ----------------
__global__ void gather_mean(const uint16_t* __restrict__ Xh) {
    int w = (blockIdx.x * blockDim.x + threadIdx.x) >> 5;
    int lane = threadIdx.x & 31;
    if (w >= N_NODES) return;
    int beg = g_rowptr[w], end = g_rowptr[w + 1];
    int half = lane >> 4;
    int l16  = lane & 15;

    float a[8];
#pragma unroll
    for (int j = 0; j < 8; j++) a[j] = 0.f;

    int e = beg + half;
    for (; e + 6 < end; e += 8) {
        int s0 = g_csr[e],     s1 = g_csr[e + 2];
        int s2 = g_csr[e + 4], s3 = g_csr[e + 6];
        uint4 u0 = ((const uint4*)(Xh + (size_t)s0 * 128))[l16];
        uint4 u1 = ((const uint4*)(Xh + (size_t)s1 * 128))[l16];
        uint4 u2 = ((const uint4*)(Xh + (size_t)s2 * 128))[l16];
        uint4 u3 = ((const uint4*)(Xh + (size_t)s3 * 128))[l16];
        float2 f;
        f = __half22float2(*(__half2*)&u0.x); a[0] += f.x; a[1] += f.y;
        f = __half22float2(*(__half2*)&u0.y); a[2] += f.x; a[3] += f.y;
        f = __half22float2(*(__half2*)&u0.z); a[4] += f.x; a[5] += f.y;
        f = __half22float2(*(__half2*)&u0.w); a[6] += f.x; a[7] += f.y;
        f = __half22float2(*(__half2*)&u1.x); a[0] += f.x; a[1] += f.y;
        f = __half22float2(*(__half2*)&u1.y); a[2] += f.x; a[3] += f.y;
        f = __half22float2(*(__half2*)&u1.z); a[4] += f.x; a[5] += f.y;
        f = __half22float2(*(__half2*)&u1.w); a[6] += f.x; a[7] += f.y;
        f = __half22float2(*(__half2*)&u2.x); a[0] += f.x; a[1] += f.y;
        f = __half22float2(*(__half2*)&u2.y); a[2] += f.x; a[3] += f.y;
        f = __half22float2(*(__half2*)&u2.z); a[4] += f.x; a[5] += f.y;
        f = __half22float2(*(__half2*)&u2.w); a[6] += f.x; a[7] += f.y;
        f = __half22float2(*(__half2*)&u3.x); a[0] += f.x; a[1] += f.y;
        f = __half22float2(*(__half2*)&u3.y); a[2] += f.x; a[3] += f.y;
        f = __half22float2(*(__half2*)&u3.z); a[4] += f.x; a[5] += f.y;
        f = __half22float2(*(__half2*)&u3.w); a[6] += f.x; a[7] += f.y;
    }
    for (; e < end; e += 2) {
        int s = g_csr[e];
        uint4 u = ((const uint4*)(Xh + (size_t)s * 128))[l16];
        float2 f;
        f = __half22float2(*(__half2*)&u.x); a[0] += f.x; a[1] += f.y;
        f = __half22float2(*(__half2*)&u.y); a[2] += f.x; a[3] += f.y;
        f = __half22float2(*(__half2*)&u.z); a[4] += f.x; a[5] += f.y;
        f = __half22float2(*(__half2*)&u.w); a[6] += f.x; a[7] += f.y;
    }
#pragma unroll
    for (int j = 0; j < 8; j++) a[j] += __shfl_down_sync(~0u, a[j], 16);

    if (half == 0) {
        float inv = 1.0f / fmaxf((float)(end - beg), 1.0f);
        __half2 h0 = __floats2half2_rn(a[0] * inv, a[1] * inv);
        __half2 h1 = __floats2half2_rn(a[2] * inv, a[3] * inv);
        __half2 h2 = __floats2half2_rn(a[4] * inv, a[5] * inv);
        __half2 h3 = __floats2half2_rn(a[6] * inv, a[7] * inv);
        uint4 o;
        o.x = *(uint32_t*)&h0; o.y = *(uint32_t*)&h1;
        o.z = *(uint32_t*)&h2; o.w = *(uint32_t*)&h3;
        ((uint4*)(g_aggh + (size_t)w * 128))[l16] = o;
    }
}

// ---------------- persistent combine: B fully resident in smem, A double-buffered ----------------
// OUT=128: Bs 67.5KB + As 18.4KB -> 2 CTAs/SM. OUT=64: 33.8+18.4 -> 4 CTAs/SM.
template <int OUT, bool RELU, bool HOUT, int OCC>
__global__ void __launch_bounds__(128, OCC) combine_mma(
    const uint16_t* __restrict__ Aagg,
    const uint16_t* __restrict__ Aroot,
    const uint16_t* __restrict__ Bw,
    const float* __restrict__ bias,
    void* __restrict__ Cout)
{
    constexpr int NA = OUT / 16;
    constexpr int NTILES = (N_NODES + 63) / 64;   // 782
    __shared__ uint32_t As[2][64][36];
    __shared__ uint32_t Bs[OUT][132];             // full K resident (128 u32 + 4 pad)

    const int tid    = threadIdx.x;
    const int wid    = tid >> 5;
    const int lane   = tid & 31;
    const int warp_m = wid >> 1;
    const int warp_n = wid & 1;
    const int g      = lane >> 2;
    const int t      = lane & 3;

    // ---- load all of B once (own cp.async group) ----
#pragma unroll
    for (int i = 0; i < OUT / 4; i++) {           // OUT*32 uint4 / 128 thr
        int idx = i * 128 + tid;
        int o = idx >> 5, q = idx & 31;
        cp16((uint32_t)__cvta_generic_to_shared(&Bs[o][q * 4]),
             Bw + (size_t)o * 256 + q * 8);
    }
    CP_COMMIT();

    auto issueA = [&](int tile, int c, int buf) {
        const int row0 = tile * 64;
        const int k0 = c * 64;
        const uint16_t* src = (k0 < 128) ? (Aagg + k0) : (Aroot + (k0 - 128));
#pragma unroll
        for (int i = 0; i < 4; i++) {
            int idx = i * 128 + tid;
            int r = idx >> 3, q = idx & 7;
            int grow = row0 + r;
            if (grow > N_NODES - 1) grow = N_NODES - 1;
            cp16((uint32_t)__cvta_generic_to_shared(&As[buf][r][q * 4]),
                 src + (size_t)grow * 128 + q * 8);
        }
        CP_COMMIT();
    };

    for (int tile = blockIdx.x; tile < NTILES; tile += gridDim.x) {
        const int row0 = tile * 64;

        float acc[2][NA][4];
#pragma unroll
        for (int m = 0; m < 2; m++)
#pragma unroll
            for (int n = 0; n < NA; n++)
#pragma unroll
                for (int j = 0; j < 4; j++) acc[m][n][j] = 0.f;

        issueA(tile, 0, 0);

        for (int c = 0; c < 4; c++) {
            if (c < 3) { issueA(tile, c + 1, (c + 1) & 1); CP_WAIT(1); }
            else       { CP_WAIT(0); }
            __syncthreads();

            const int buf = c & 1;
            const int kb  = c * 32;               // u32 offset into resident B
#pragma unroll
            for (int ks = 0; ks < 4; ks++) {
                const int off = ks * 8;
                uint32_t a[2][4];
#pragma unroll
                for (int m = 0; m < 2; m++) {
                    int row = warp_m * 32 + m * 16 + g;
                    a[m][0] = As[buf][row][off + t];
                    a[m][1] = As[buf][row + 8][off + t];
                    a[m][2] = As[buf][row][off + t + 4];
                    a[m][3] = As[buf][row + 8][off + t + 4];
                }
                uint32_t b[NA][2];
#pragma unroll
                for (int n = 0; n < NA; n++) {
                    int col = warp_n * (OUT / 2) + n * 8 + g;
                    b[n][0] = Bs[col][kb + off + t];
                    b[n][1] = Bs[col][kb + off + t + 4];
                }
#pragma unroll
                for (int m = 0; m < 2; m++)
#pragma unroll
                    for (int n = 0; n < NA; n++)
                        mma_f16(acc[m][n], a[m], b[n]);
            }
            __syncthreads();
        }

        // ---- epilogue ----
#pragma unroll
        for (int m = 0; m < 2; m++) {
            int r_lo = row0 + warp_m * 32 + m * 16 + g;
            int r_hi = r_lo + 8;
#pragma unroll
            for (int n = 0; n < NA; n++) {
                int col = warp_n * (OUT / 2) + n * 8 + t * 2;
                float bx = bias[col], by = bias[col + 1];
                float v0 = acc[m][n][0] + bx, v1 = acc[m][n][1] + by;
                float v2 = acc[m][n][2] + bx, v3 = acc[m][n][3] + by;
                if (RELU) {
                    v0 = fmaxf(v0, 0.f); v1 = fmaxf(v1, 0.f);
                    v2 = fmaxf(v2, 0.f); v3 = fmaxf(v3, 0.f);
                }
                if (HOUT) {
                    uint16_t* C = (uint16_t*)Cout;
                    __half2 lo = __floats2half2_rn(v0, v1);
                    __half2 hi = __floats2half2_rn(v2, v3);
                    if (r_lo < N_NODES) *(uint32_t*)(C + (size_t)r_lo * OUT + col) = *(uint32_t*)&lo;
                    if (r_hi < N_NODES) *(uint32_t*)(C + (size_t)r_hi * OUT + col) = *(uint32_t*)&hi;
                } else {
                    float* C = (float*)Cout;
                    if (r_lo < N_NODES) *(float2*)(C + (size_t)r_lo * OUT + col) = make_float2(v0, v1);
                    if (r_hi < N_NODES) *(float2*)(C + (size_t)r_hi * OUT + col) = make_float2(v2, v3);
                }
            }
        }
    }
}

// ---------------- host launch ----------------
extern "C" void kernel_launch(void* const* d_in, const int* in_sizes, int n_in,
                              void* d_out, int out_size) {
    const float* x   = (const float*)d_in[0];
    const void*  ei  = d_in[1];
    const float* w1n = (const float*)d_in[2];
    const float* w1r = (const float*)d_in[3];
    const float* b1  = (const float*)d_in[4];
    const float* w2n = (const float*)d_in[5];
    const float* w2r = (const float*)d_in[6];
    const float* b2  = (const float*)d_in[7];
    const float* w3n = (const float*)d_in[8];
    const float* w3r = (const float*)d_in[9];
    const float* b3  = (const float*)d_in[10];

    int* ideg;
    uint16_t *xh, *aggh, *h1h, *h2h, *B1, *B2, *B3;
    cudaGetSymbolAddress((void**)&ideg, g_ideg);
    cudaGetSymbolAddress((void**)&xh,   g_xh);
    cudaGetSymbolAddress((void**)&aggh, g_aggh);
    cudaGetSymbolAddress((void**)&h1h,  g_h1h);
    cudaGetSymbolAddress((void**)&h2h,  g_h2h);
    cudaGetSymbolAddress((void**)&B1,   g_B1);
    cudaGetSymbolAddress((void**)&B2,   g_B2);
    cudaGetSymbolAddress((void**)&B3,   g_B3);

    const int TPB = 256;
    const int gatherBlocks = (N_NODES * 32 + TPB - 1) / TPB;              // 6250
    const int prepBlocks   = (N_NODES * 64 + 81920 + TPB - 1) / TPB;      // 12820
    const int gemm128Grid  = 296;   // 2 CTAs/SM x 148 SMs (86KB smem/CTA)
    const int gemm64Grid   = 592;   // 4 CTAs/SM (52KB smem/CTA)

    // ---- structure + CSR + prep ----
    cudaMemsetAsync(ideg, 0, 50048 * sizeof(int));
    deg_prep<<<EDGE_BLOCKS4 + prepBlocks, TPB>>>(ei, x, w1n, w1r, w2n, w2r, w3n, w3r);
    scan_local<<<196, 256>>>();
    scan_add_full<<<196, 256>>>();
    fill_csr<<<EDGE_BLOCKS4, TPB>>>(ei);

    // ---- layer 1 ----
    gather_mean<<<gatherBlocks, TPB>>>(xh);
    combine_mma<128, true, true, 2><<<gemm128Grid, 128>>>(aggh, xh, B1, b1, h1h);

    // ---- layer 2 ----
    gather_mean<<<gatherBlocks, TPB>>>(h1h);
    combine_mma<128, true, true, 2><<<gemm128Grid, 128>>>(aggh, h1h, B2, b2, h2h);

    // ---- layer 3 ----
    gather_mean<<<gatherBlocks, TPB>>>(h2h);
    combine_mma<64, false, false, 4><<<gemm64Grid, 128>>>(aggh, h2h, B3, b3, d_out);
}

// round 15
// speedup vs baseline: 1.6718x; 1.0164x over previous
#include <cuda_runtime.h>
#include <cuda_fp16.h>
#include <cstdint>

#define N_NODES 50000
#define N_EDGES 600000
#define EDGE_BLOCKS4 586          // ceil(600000 / 1024), 4 edges per thread

// ---------------- scratch (static __device__, no allocations) ----------------
__device__ int      g_csr[N_EDGES];
__device__ int      g_ideg[50048];
__device__ int      g_rowptr[N_NODES + 1];
__device__ volatile int g_aggS[256];              // lookback aggregates (sentinel -1)
__device__ int      g_cnt[50048];                 // seeded with rowptr by scan_one
__device__ uint16_t g_aggh[(size_t)N_NODES * 128];
__device__ uint16_t g_xh  [(size_t)N_NODES * 128];
__device__ uint16_t g_h1h [(size_t)N_NODES * 128];
__device__ uint16_t g_h2h [(size_t)N_NODES * 128];
__device__ uint16_t g_B1[128 * 256];
__device__ uint16_t g_B2[128 * 256];
__device__ uint16_t g_B3[64 * 256];

// ---------------- mma / cp.async / ldmatrix helpers ----------------
__device__ __forceinline__ void mma_f16(float* d, const uint32_t* a, const uint32_t* b) {
    asm volatile(
        "mma.sync.aligned.m16n8k16.row.col.f32.f16.f16.f32 "
        "{%0,%1,%2,%3}, {%4,%5,%6,%7}, {%8,%9}, {%0,%1,%2,%3};"
        : "+f"(d[0]), "+f"(d[1]), "+f"(d[2]), "+f"(d[3])
        : "r"(a[0]), "r"(a[1]), "r"(a[2]), "r"(a[3]), "r"(b[0]), "r"(b[1]));
}
__device__ __forceinline__ void cp16(uint32_t smem, const void* g) {
    asm volatile("cp.async.ca.shared.global [%0], [%1], 16;" :: "r"(smem), "l"(g));
}
#define CP_COMMIT() asm volatile("cp.async.commit_group;")
#define CP_WAIT(N)  asm volatile("cp.async.wait_group %0;" :: "n"(N))
__device__ __forceinline__ void ldsm_x4(uint32_t* r, uint32_t addr) {
    asm volatile("ldmatrix.sync.aligned.m8n8.x4.shared.b16 {%0,%1,%2,%3}, [%4];"
                 : "=r"(r[0]), "=r"(r[1]), "=r"(r[2]), "=r"(r[3]) : "r"(addr));
}

// ---- dtype sniff: int64 LE edge indices (< 50000) have ALL odd 32-bit words zero.
__device__ __forceinline__ bool sniff_is64(const unsigned int* p32) {
    bool is64 = true;
#pragma unroll
    for (int j = 1; j < 32; j += 2) is64 &= (p32[j] == 0u);
    return is64;
}
__device__ __forceinline__ void load_edge(const void* p, bool is64, int e, int& s, int& d) {
    if (is64) {
        const long long* q = (const long long*)p;
        s = (int)q[e];
        d = (int)q[N_EDGES + e];
    } else {
        const int* q = (const int*)p;
        s = q[e];
        d = q[N_EDGES + e];
    }
}

// ---------------- structure: degree histogram (4 edges/thread) + fp16 prep ----------------
__global__ void deg_prep(const void* p, const float* __restrict__ x,
                         const float* w1n, const float* w1r,
                         const float* w2n, const float* w2r,
                         const float* w3n, const float* w3r) {
    int b = blockIdx.x;
    if (b < EDGE_BLOCKS4) {
        if (b == 0) g_aggS[threadIdx.x] = -1;     // sentinel reset for scan_one
        bool is64 = sniff_is64((const unsigned int*)p);
        int base = b * 1024 + threadIdx.x;
        int d[4];
#pragma unroll
        for (int k = 0; k < 4; k++) {
            int e = base + k * 256;
            if (e < N_EDGES) {
                int s;
                load_edge(p, is64, e, s, d[k]);
            } else d[k] = -1;
        }
#pragma unroll
        for (int k = 0; k < 4; k++)
            if (d[k] >= 0) atomicAdd(&g_ideg[d[k]], 1);
        return;
    }
    int i = (b - EDGE_BLOCKS4) * 256 + threadIdx.x;
    const int NX = N_NODES * 64;                  // half2 count for x
    if (i < NX) {
        float2 v = ((const float2*)x)[i];
        ((__half2*)g_xh)[i] = __floats2half2_rn(v.x, v.y);
        return;
    }
    int idx = i - NX;
    if (idx < 32768) {
        int o = idx >> 8, k = idx & 255;
        float v = (k < 128) ? w1n[o * 128 + k] : w1r[o * 128 + (k - 128)];
        g_B1[idx] = __half_as_ushort(__float2half_rn(v));
    } else if (idx < 65536) {
        int j = idx - 32768;
        int o = j >> 8, k = j & 255;
        float v = (k < 128) ? w2n[o * 128 + k] : w2r[o * 128 + (k - 128)];
        g_B2[j] = __half_as_ushort(__float2half_rn(v));
    } else if (idx < 81920) {
        int j = idx - 65536;
        int o = j >> 8, k = j & 255;
        float v = (k < 128) ? w3n[o * 128 + k] : w3r[o * 128 + (k - 128)];
        g_B3[j] = __half_as_ushort(__float2half_rn(v));
    }
}

// ---- single-kernel scan: local scan + decoupled-lookback across 196 blocks ----
__global__ void scan_one() {              // grid 196, block 256 (all co-resident)
    __shared__ int wtot[8];
    __shared__ int wsum[8];
    __shared__ int pref_s;
    int b = blockIdx.x, t = threadIdx.x, i = b * 256 + t;
    int lane = t & 31, wid = t >> 5;
    int v = (i < N_NODES) ? g_ideg[i] : 0;
    int x = v;
#pragma unroll
    for (int o = 1; o < 32; o <<= 1) {
        int y = __shfl_up_sync(~0u, x, o);
        if (lane >= o) x += y;
    }
    if (lane == 31) wtot[wid] = x;
    __syncthreads();
    if (wid == 0) {
        int w = (lane < 8) ? wtot[lane] : 0;
#pragma unroll
        for (int o = 1; o < 8; o <<= 1) {
            int y = __shfl_up_sync(0xffffffffu, w, o);
            if (lane >= o) w += y;
        }
        if (lane < 8) wtot[lane] = w;
    }
    __syncthreads();
    int excl = x - v + (wid > 0 ? wtot[wid - 1] : 0);

    // publish this block's aggregate
    if (t == 0) {
        g_aggS[b] = wtot[7];
        __threadfence();
    }
    // lookback: sum predecessors' aggregates (parallel across threads)
    int mysum = 0;
    for (int j = t; j < b; j += 256) {
        int vv;
        do { vv = g_aggS[j]; } while (vv == -1);
        mysum += vv;
    }
#pragma unroll
    for (int o = 16; o > 0; o >>= 1) mysum += __shfl_down_sync(~0u, mysum, o);
    if (lane == 0) wsum[wid] = mysum;
    __syncthreads();
    if (t == 0) {
        int s = 0;
#pragma unroll
        for (int j = 0; j < 8; j++) s += wsum[j];
        pref_s = s;
    }
    __syncthreads();
    if (i < N_NODES) {
        int r = excl + pref_s;
        g_rowptr[i] = r;
        g_cnt[i]    = r;                   // seed fill cursor
    }
    if (b == 0 && t == 0) g_rowptr[N_NODES] = N_EDGES;
}

// ---- fill: 4 edges per thread, loads batched ahead of atomics ----
__global__ void fill_csr(const void* p) {
    bool is64 = sniff_is64((const unsigned int*)p);
    int base = blockIdx.x * 1024 + threadIdx.x;
    int s[4], d[4];
#pragma unroll
    for (int k = 0; k < 4; k++) {
        int e = base + k * 256;
        if (e < N_EDGES) load_edge(p, is64, e, s[k], d[k]);
        else d[k] = -1;
    }
#pragma unroll
    for (int k = 0; k < 4; k++) {
        if (d[k] >= 0) {
            int pos = atomicAdd(&g_cnt[d[k]], 1);
            g_csr[pos] = s[k];
        }
    }
}

// ---------------- gather-mean: one warp per node, 2 half-warps, 4-deep MLP ----------------
__global__ void gather_mean(const uint16_t* __restrict__ Xh) {
    int w = (blockIdx.x * blockDim.x + threadIdx.x) >> 5;
    int lane = threadIdx.x & 31;
    if (w >= N_NODES) return;
    int beg = g_rowptr[w], end = g_rowptr[w + 1];
    int half = lane >> 4;
    int l16  = lane & 15;

    float a[8];
#pragma unroll
    for (int j = 0; j < 8; j++) a[j] = 0.f;

    int e = beg + half;
    for (; e + 6 < end; e += 8) {
        int s0 = g_csr[e],     s1 = g_csr[e + 2];
        int s2 = g_csr[e + 4], s3 = g_csr[e + 6];
        uint4 u0 = ((const uint4*)(Xh + (size_t)s0 * 128))[l16];
        uint4 u1 = ((const uint4*)(Xh + (size_t)s1 * 128))[l16];
        uint4 u2 = ((const uint4*)(Xh + (size_t)s2 * 128))[l16];
        uint4 u3 = ((const uint4*)(Xh + (size_t)s3 * 128))[l16];
        float2 f;
        f = __half22float2(*(__half2*)&u0.x); a[0] += f.x; a[1] += f.y;
        f = __half22float2(*(__half2*)&u0.y); a[2] += f.x; a[3] += f.y;
        f = __half22float2(*(__half2*)&u0.z); a[4] += f.x; a[5] += f.y;
        f = __half22float2(*(__half2*)&u0.w); a[6] += f.x; a[7] += f.y;
        f = __half22float2(*(__half2*)&u1.x); a[0] += f.x; a[1] += f.y;
        f = __half22float2(*(__half2*)&u1.y); a[2] += f.x; a[3] += f.y;
        f = __half22float2(*(__half2*)&u1.z); a[4] += f.x; a[5] += f.y;
        f = __half22float2(*(__half2*)&u1.w); a[6] += f.x; a[7] += f.y;
        f = __half22float2(*(__half2*)&u2.x); a[0] += f.x; a[1] += f.y;
        f = __half22float2(*(__half2*)&u2.y); a[2] += f.x; a[3] += f.y;
        f = __half22float2(*(__half2*)&u2.z); a[4] += f.x; a[5] += f.y;
        f = __half22float2(*(__half2*)&u2.w); a[6] += f.x; a[7] += f.y;
        f = __half22float2(*(__half2*)&u3.x); a[0] += f.x; a[1] += f.y;
        f = __half22float2(*(__half2*)&u3.y); a[2] += f.x; a[3] += f.y;
        f = __half22float2(*(__half2*)&u3.z); a[4] += f.x; a[5] += f.y;
        f = __half22float2(*(__half2*)&u3.w); a[6] += f.x; a[7] += f.y;
    }
    for (; e < end; e += 2) {
        int s = g_csr[e];
        uint4 u = ((const uint4*)(Xh + (size_t)s * 128))[l16];
        float2 f;
        f = __half22float2(*(__half2*)&u.x); a[0] += f.x; a[1] += f.y;
        f = __half22float2(*(__half2*)&u.y); a[2] += f.x; a[3] += f.y;
        f = __half22float2(*(__half2*)&u.z); a[4] += f.x; a[5] += f.y;
        f = __half22float2(*(__half2*)&u.w); a[6] += f.x; a[7] += f.y;
    }
#pragma unroll
    for (int j = 0; j < 8; j++) a[j] += __shfl_down_sync(~0u, a[j], 16);

    if (half == 0) {
        float inv = 1.0f / fmaxf((float)(end - beg), 1.0f);
        __half2 h0 = __floats2half2_rn(a[0] * inv, a[1] * inv);
        __half2 h1 = __floats2half2_rn(a[2] * inv, a[3] * inv);
        __half2 h2 = __floats2half2_rn(a[4] * inv, a[5] * inv);
        __half2 h3 = __floats2half2_rn(a[6] * inv, a[7] * inv);
        uint4 o;
        o.x = *(uint32_t*)&h0; o.y = *(uint32_t*)&h1;
        o.z = *(uint32_t*)&h2; o.w = *(uint32_t*)&h3;
        ((uint4*)(g_aggh + (size_t)w * 128))[l16] = o;
    }
}

// ---------------- persistent combine: resident B, A double-buffered, ldmatrix frags ----------------
template <int OUT, bool RELU, bool HOUT, int OCC>
__global__ void __launch_bounds__(128, OCC) combine_mma(
    const uint16_t* __restrict__ Aagg,
    const uint16_t* __restrict__ Aroot,
    const uint16_t* __restrict__ Bw,
    const float* __restrict__ bias,
    void* __restrict__ Cout)
{
    constexpr int NA = OUT / 16;
    constexpr int NP = NA / 2;                    // ldmatrix n-atom pairs
    constexpr int NTILES = (N_NODES + 63) / 64;   // 782
    __shared__ uint32_t As[2][64][36];
    __shared__ uint32_t Bs[OUT][132];             // full K resident

    const int tid    = threadIdx.x;
    const int wid    = tid >> 5;
    const int lane   = tid & 31;
    const int warp_m = wid >> 1;
    const int warp_n = wid & 1;
    const int g      = lane >> 2;
    const int t      = lane & 3;

    // ---- ldmatrix per-lane base addresses ----
    const int lj = lane & 7;                      // row within m8n8
    const int lk = (lane >> 3) & 1;               // matrix pair selector
    const int lh = lane >> 4;                     // upper/lower half
    uint32_t aBase[2];
#pragma unroll
    for (int m = 0; m < 2; m++) {
        int row = warp_m * 32 + m * 16 + lj + lk * 8;
        aBase[m] = (uint32_t)__cvta_generic_to_shared(&As[0][row][lh * 4]);
    }
    uint32_t bBase[NP];
#pragma unroll
    for (int p = 0; p < NP; p++) {
        int col = warp_n * (OUT / 2) + (p * 2 + lh) * 8 + lj;
        bBase[p] = (uint32_t)__cvta_generic_to_shared(&Bs[col][lk * 4]);
    }
    constexpr uint32_t ABUF = 64 * 36 * 4;        // bytes per A buffer

    // ---- load all of B once ----
#pragma unroll
    for (int i = 0; i < OUT / 4; i++) {
        int idx = i * 128 + tid;
        int o = idx >> 5, q = idx & 31;
        cp16((uint32_t)__cvta_generic_to_shared(&Bs[o][q * 4]),
             Bw + (size_t)o * 256 + q * 8);
    }
    CP_COMMIT();

    auto issueA = [&](int tile, int c, int buf) {
        const int row0 = tile * 64;
        const int k0 = c * 64;
        const uint16_t* src = (k0 < 128) ? (Aagg + k0) : (Aroot + (k0 - 128));
#pragma unroll
        for (int i = 0; i < 4; i++) {
            int idx = i * 128 + tid;
            int r = idx >> 3, q = idx & 7;
            int grow = row0 + r;
            if (grow > N_NODES - 1) grow = N_NODES - 1;
            cp16((uint32_t)__cvta_generic_to_shared(&As[buf][r][q * 4]),
                 src + (size_t)grow * 128 + q * 8);
        }
        CP_COMMIT();
    };

    for (int tile = blockIdx.x; tile < NTILES; tile += gridDim.x) {
        const int row0 = tile * 64;

        float acc[2][NA][4];
#pragma unroll
        for (int m = 0; m < 2; m++)
#pragma unroll
            for (int n = 0; n < NA; n++)
#pragma unroll
                for (int j = 0; j < 4; j++) acc[m][n][j] = 0.f;

        issueA(tile, 0, 0);

        for (int c = 0; c < 4; c++) {
            if (c < 3) { issueA(tile, c + 1, (c + 1) & 1); CP_WAIT(1); }
            else       { CP_WAIT(0); }
            __syncthreads();

            const int buf = c & 1;
            const int kb  = c * 32;               // u32 offset into resident B
#pragma unroll
            for (int ks = 0; ks < 4; ks++) {
                const int off = ks * 8;
                uint32_t a[2][4];
#pragma unroll
                for (int m = 0; m < 2; m++)
                    ldsm_x4(a[m], aBase[m] + buf * ABUF + off * 4);
                uint32_t b[NA][2];
#pragma unroll
                for (int p = 0; p < NP; p++) {
                    uint32_t br[4];
                    ldsm_x4(br, bBase[p] + (kb + off) * 4);
                    b[p * 2][0] = br[0]; b[p * 2][1] = br[1];
                    b[p * 2 + 1][0] = br[2]; b[p * 2 + 1][1] = br[3];
                }
#pragma unroll
                for (int m = 0; m < 2; m++)
#pragma unroll
                    for (int n = 0; n < NA; n++)
                        mma_f16(acc[m][n], a[m], b[n]);
            }
            __syncthreads();
        }

        // ---- epilogue ----
#pragma unroll
        for (int m = 0; m < 2; m++) {
            int r_lo = row0 + warp_m * 32 + m * 16 + g;
            int r_hi = r_lo + 8;
#pragma unroll
            for (int n = 0; n < NA; n++) {
                int col = warp_n * (OUT / 2) + n * 8 + t * 2;
                float bx = bias[col], by = bias[col + 1];
                float v0 = acc[m][n][0] + bx, v1 = acc[m][n][1] + by;
                float v2 = acc[m][n][2] + bx, v3 = acc[m][n][3] + by;
                if (RELU) {
                    v0 = fmaxf(v0, 0.f); v1 = fmaxf(v1, 0.f);
                    v2 = fmaxf(v2, 0.f); v3 = fmaxf(v3, 0.f);
                }
                if (HOUT) {
                    uint16_t* C = (uint16_t*)Cout;
                    __half2 lo = __floats2half2_rn(v0, v1);
                    __half2 hi = __floats2half2_rn(v2, v3);
                    if (r_lo < N_NODES) *(uint32_t*)(C + (size_t)r_lo * OUT + col) = *(uint32_t*)&lo;
                    if (r_hi < N_NODES) *(uint32_t*)(C + (size_t)r_hi * OUT + col) = *(uint32_t*)&hi;
                } else {
                    float* C = (float*)Cout;
                    if (r_lo < N_NODES) *(float2*)(C + (size_t)r_lo * OUT + col) = make_float2(v0, v1);
                    if (r_hi < N_NODES) *(float2*)(C + (size_t)r_hi * OUT + col) = make_float2(v2, v3);
                }
            }
        }
    }
}

// ---------------- host launch ----------------
extern "C" void kernel_launch(void* const* d_in, const int* in_sizes, int n_in,
                              void* d_out, int out_size) {
    const float* x   = (const float*)d_in[0];
    const void*  ei  = d_in[1];
    const float* w1n = (const float*)d_in[2];
    const float* w1r = (const float*)d_in[3];
    const float* b1  = (const float*)d_in[4];
    const float* w2n = (const float*)d_in[5];
    const float* w2r = (const float*)d_in[6];
    const float* b2  = (const float*)d_in[7];
    const float* w3n = (const float*)d_in[8];
    const float* w3r = (const float*)d_in[9];
    const float* b3  = (const float*)d_in[10];

    int* ideg;
    uint16_t *xh, *aggh, *h1h, *h2h, *B1, *B2, *B3;
    cudaGetSymbolAddress((void**)&ideg, g_ideg);
    cudaGetSymbolAddress((void**)&xh,   g_xh);
    cudaGetSymbolAddress((void**)&aggh, g_aggh);
    cudaGetSymbolAddress((void**)&h1h,  g_h1h);
    cudaGetSymbolAddress((void**)&h2h,  g_h2h);
    cudaGetSymbolAddress((void**)&B1,   g_B1);
    cudaGetSymbolAddress((void**)&B2,   g_B2);
    cudaGetSymbolAddress((void**)&B3,   g_B3);

    const int TPB = 256;
    const int gatherBlocks = (N_NODES * 32 + TPB - 1) / TPB;              // 6250
    const int prepBlocks   = (N_NODES * 64 + 81920 + TPB - 1) / TPB;      // 12820
    const int gemm128Grid  = 296;   // 2 CTAs/SM (86KB smem/CTA)
    const int gemm64Grid   = 592;   // 4 CTAs/SM (52KB smem/CTA)

    // ---- structure + CSR + prep ----
    cudaMemsetAsync(ideg, 0, 50048 * sizeof(int));
    deg_prep<<<EDGE_BLOCKS4 + prepBlocks, TPB>>>(ei, x, w1n, w1r, w2n, w2r, w3n, w3r);
    scan_one<<<196, 256>>>();
    fill_csr<<<EDGE_BLOCKS4, TPB>>>(ei);

    // ---- layer 1 ----
    gather_mean<<<gatherBlocks, TPB>>>(xh);
    combine_mma<128, true, true, 2><<<gemm128Grid, 128>>>(aggh, xh, B1, b1, h1h);

    // ---- layer 2 ----
    gather_mean<<<gatherBlocks, TPB>>>(h1h);
    combine_mma<128, true, true, 2><<<gemm128Grid, 128>>>(aggh, h1h, B2, b2, h2h);

    // ---- layer 3 ----
    gather_mean<<<gatherBlocks, TPB>>>(h2h);
    combine_mma<64, false, false, 4><<<gemm64Grid, 128>>>(aggh, h2h, B3, b3, d_out);
}

// round 17
// speedup vs baseline: 1.7193x; 1.0284x over previous
#include <cuda_runtime.h>
#include <cuda_fp16.h>
#include <cstdint>

#define N_NODES 50000
#define N_EDGES 600000
#define EDGE_BLOCKS4 586          // ceil(600000 / 1024), 4 edges per thread

// ---------------- scratch (static __device__, no allocations) ----------------
__device__ int      g_csr[N_EDGES];
__device__ int      g_ideg[50048];
__device__ int      g_rowptr[N_NODES + 1];
__device__ volatile int g_aggS[256];              // lookback aggregates (sentinel -1)
__device__ int      g_cnt[50048];                 // seeded with rowptr by scan_one
__device__ uint16_t g_aggh[(size_t)N_NODES * 128];
__device__ uint16_t g_xh  [(size_t)N_NODES * 128];
__device__ uint16_t g_h1h [(size_t)N_NODES * 128];
__device__ uint16_t g_h2h [(size_t)N_NODES * 128];
__device__ uint16_t g_B1[128 * 256];
__device__ uint16_t g_B2[128 * 256];
__device__ uint16_t g_B3[64 * 256];

// ---------------- mma / cp.async / ldmatrix helpers ----------------
__device__ __forceinline__ void mma_f16(float* d, const uint32_t* a, const uint32_t* b) {
    asm volatile(
        "mma.sync.aligned.m16n8k16.row.col.f32.f16.f16.f32 "
        "{%0,%1,%2,%3}, {%4,%5,%6,%7}, {%8,%9}, {%0,%1,%2,%3};"
        : "+f"(d[0]), "+f"(d[1]), "+f"(d[2]), "+f"(d[3])
        : "r"(a[0]), "r"(a[1]), "r"(a[2]), "r"(a[3]), "r"(b[0]), "r"(b[1]));
}
__device__ __forceinline__ void cp16(uint32_t smem, const void* g) {
    asm volatile("cp.async.ca.shared.global [%0], [%1], 16;" :: "r"(smem), "l"(g));
}
#define CP_COMMIT() asm volatile("cp.async.commit_group;")
#define CP_WAIT(N)  asm volatile("cp.async.wait_group %0;" :: "n"(N))
__device__ __forceinline__ void ldsm_x4(uint32_t* r, uint32_t addr) {
    asm volatile("ldmatrix.sync.aligned.m8n8.x4.shared.b16 {%0,%1,%2,%3}, [%4];"
                 : "=r"(r[0]), "=r"(r[1]), "=r"(r[2]), "=r"(r[3]) : "r"(addr));
}

// ---- dtype sniff: int64 LE edge indices (< 50000) have ALL odd 32-bit words zero.
__device__ __forceinline__ bool sniff_is64(const unsigned int* p32) {
    bool is64 = true;
#pragma unroll
    for (int j = 1; j < 32; j += 2) is64 &= (p32[j] == 0u);
    return is64;
}
__device__ __forceinline__ void load_edge(const void* p, bool is64, int e, int& s, int& d) {
    if (is64) {
        const long long* q = (const long long*)p;
        s = (int)q[e];
        d = (int)q[N_EDGES + e];
    } else {
        const int* q = (const int*)p;
        s = q[e];
        d = q[N_EDGES + e];
    }
}

// ---------------- structure: degree histogram (4 edges/thread) + fp16 prep ----------------
__global__ void deg_prep(const void* p, const float* __restrict__ x,
                         const float* w1n, const float* w1r,
                         const float* w2n, const float* w2r,
                         const float* w3n, const float* w3r) {
    int b = blockIdx.x;
    if (b < EDGE_BLOCKS4) {
        if (b == 0) g_aggS[threadIdx.x] = -1;     // sentinel reset for scan_one
        bool is64 = sniff_is64((const unsigned int*)p);
        int base = b * 1024 + threadIdx.x;
        int d[4];
#pragma unroll
        for (int k = 0; k < 4; k++) {
            int e = base + k * 256;
            if (e < N_EDGES) {
                int s;
                load_edge(p, is64, e, s, d[k]);
            } else d[k] = -1;
        }
#pragma unroll
        for (int k = 0; k < 4; k++)
            if (d[k] >= 0) atomicAdd(&g_ideg[d[k]], 1);
        return;
    }
    int i = (b - EDGE_BLOCKS4) * 256 + threadIdx.x;
    const int NX = N_NODES * 64;                  // half2 count for x
    if (i < NX) {
        float2 v = ((const float2*)x)[i];
        ((__half2*)g_xh)[i] = __floats2half2_rn(v.x, v.y);
        return;
    }
    int idx = i - NX;
    if (idx < 32768) {
        int o = idx >> 8, k = idx & 255;
        float v = (k < 128) ? w1n[o * 128 + k] : w1r[o * 128 + (k - 128)];
        g_B1[idx] = __half_as_ushort(__float2half_rn(v));
    } else if (idx < 65536) {
        int j = idx - 32768;
        int o = j >> 8, k = j & 255;
        float v = (k < 128) ? w2n[o * 128 + k] : w2r[o * 128 + (k - 128)];
        g_B2[j] = __half_as_ushort(__float2half_rn(v));
    } else if (idx < 81920) {
        int j = idx - 65536;
        int o = j >> 8, k = j & 255;
        float v = (k < 128) ? w3n[o * 128 + k] : w3r[o * 128 + (k - 128)];
        g_B3[j] = __half_as_ushort(__float2half_rn(v));
    }
}

// ---- single-kernel scan: local scan + decoupled-lookback across 196 blocks ----
__global__ void scan_one() {              // grid 196, block 256 (all co-resident)
    __shared__ int wtot[8];
    __shared__ int wsum[8];
    __shared__ int pref_s;
    int b = blockIdx.x, t = threadIdx.x, i = b * 256 + t;
    int lane = t & 31, wid = t >> 5;
    int v = (i < N_NODES) ? g_ideg[i] : 0;
    int x = v;
#pragma unroll
    for (int o = 1; o < 32; o <<= 1) {
        int y = __shfl_up_sync(~0u, x, o);
        if (lane >= o) x += y;
    }
    if (lane == 31) wtot[wid] = x;
    __syncthreads();
    if (wid == 0) {
        int w = (lane < 8) ? wtot[lane] : 0;
#pragma unroll
        for (int o = 1; o < 8; o <<= 1) {
            int y = __shfl_up_sync(0xffffffffu, w, o);
            if (lane >= o) w += y;
        }
        if (lane < 8) wtot[lane] = w;
    }
    __syncthreads();
    int excl = x - v + (wid > 0 ? wtot[wid - 1] : 0);

    if (t == 0) {
        g_aggS[b] = wtot[7];
        __threadfence();
    }
    int mysum = 0;
    for (int j = t; j < b; j += 256) {
        int vv;
        do { vv = g_aggS[j]; } while (vv == -1);
        mysum += vv;
    }
#pragma unroll
    for (int o = 16; o > 0; o >>= 1) mysum += __shfl_down_sync(~0u, mysum, o);
    if (lane == 0) wsum[wid] = mysum;
    __syncthreads();
    if (t == 0) {
        int s = 0;
#pragma unroll
        for (int j = 0; j < 8; j++) s += wsum[j];
        pref_s = s;
    }
    __syncthreads();
    if (i < N_NODES) {
        int r = excl + pref_s;
        g_rowptr[i] = r;
        g_cnt[i]    = r;                   // seed fill cursor
    }
    if (b == 0 && t == 0) g_rowptr[N_NODES] = N_EDGES;
}

// ---- fill: 4 edges per thread, loads batched ahead of atomics ----
__global__ void fill_csr(const void* p) {
    bool is64 = sniff_is64((const unsigned int*)p);
    int base = blockIdx.x * 1024 + threadIdx.x;
    int s[4], d[4];
#pragma unroll
    for (int k = 0; k < 4; k++) {
        int e = base + k * 256;
        if (e < N_EDGES) load_edge(p, is64, e, s[k], d[k]);
        else d[k] = -1;
    }
#pragma unroll
    for (int k = 0; k < 4; k++) {
        if (d[k] >= 0) {
            int pos = atomicAdd(&g_cnt[d[k]], 1);
            g_csr[pos] = s[k];
        }
    }
}

// ---------------- gather-mean: pairwise HADD2 then fp32 accumulate ----------------
__global__ void gather_mean(const uint16_t* __restrict__ Xh) {
    int w = (blockIdx.x * blockDim.x + threadIdx.x) >> 5;
    int lane = threadIdx.x & 31;
    if (w >= N_NODES) return;
    int beg = g_rowptr[w], end = g_rowptr[w + 1];
    int half = lane >> 4;
    int l16  = lane & 15;

    float a[8];
#pragma unroll
    for (int j = 0; j < 8; j++) a[j] = 0.f;

    int e = beg + half;
    for (; e + 6 < end; e += 8) {
        int s0 = g_csr[e],     s1 = g_csr[e + 2];
        int s2 = g_csr[e + 4], s3 = g_csr[e + 6];
        uint4 u0 = ((const uint4*)(Xh + (size_t)s0 * 128))[l16];
        uint4 u1 = ((const uint4*)(Xh + (size_t)s1 * 128))[l16];
        uint4 u2 = ((const uint4*)(Xh + (size_t)s2 * 128))[l16];
        uint4 u3 = ((const uint4*)(Xh + (size_t)s3 * 128))[l16];
        // pairwise fp16 sums: one rounding per pair (error << fp16 eps of final mean)
        __half2 p0 = __hadd2(*(__half2*)&u0.x, *(__half2*)&u1.x);
        __half2 p1 = __hadd2(*(__half2*)&u0.y, *(__half2*)&u1.y);
        __half2 p2 = __hadd2(*(__half2*)&u0.z, *(__half2*)&u1.z);
        __half2 p3 = __hadd2(*(__half2*)&u0.w, *(__half2*)&u1.w);
        __half2 q0 = __hadd2(*(__half2*)&u2.x, *(__half2*)&u3.x);
        __half2 q1 = __hadd2(*(__half2*)&u2.y, *(__half2*)&u3.y);
        __half2 q2 = __hadd2(*(__half2*)&u2.z, *(__half2*)&u3.z);
        __half2 q3 = __hadd2(*(__half2*)&u2.w, *(__half2*)&u3.w);
        float2 f;
        f = __half22float2(p0); a[0] += f.x; a[1] += f.y;
        f = __half22float2(p1); a[2] += f.x; a[3] += f.y;
        f = __half22float2(p2); a[4] += f.x; a[5] += f.y;
        f = __half22float2(p3); a[6] += f.x; a[7] += f.y;
        f = __half22float2(q0); a[0] += f.x; a[1] += f.y;
        f = __half22float2(q1); a[2] += f.x; a[3] += f.y;
        f = __half22float2(q2); a[4] += f.x; a[5] += f.y;
        f = __half22float2(q3); a[6] += f.x; a[7] += f.y;
    }
    for (; e < end; e += 2) {
        int s = g_csr[e];
        uint4 u = ((const uint4*)(Xh + (size_t)s * 128))[l16];
        float2 f;
        f = __half22float2(*(__half2*)&u.x); a[0] += f.x; a[1] += f.y;
        f = __half22float2(*(__half2*)&u.y); a[2] += f.x; a[3] += f.y;
        f = __half22float2(*(__half2*)&u.z); a[4] += f.x; a[5] += f.y;
        f = __half22float2(*(__half2*)&u.w); a[6] += f.x; a[7] += f.y;
    }
#pragma unroll
    for (int j = 0; j < 8; j++) a[j] += __shfl_down_sync(~0u, a[j], 16);

    if (half == 0) {
        float inv = 1.0f / fmaxf((float)(end - beg), 1.0f);
        __half2 h0 = __floats2half2_rn(a[0] * inv, a[1] * inv);
        __half2 h1 = __floats2half2_rn(a[2] * inv, a[3] * inv);
        __half2 h2 = __floats2half2_rn(a[4] * inv, a[5] * inv);
        __half2 h3 = __floats2half2_rn(a[6] * inv, a[7] * inv);
        uint4 o;
        o.x = *(uint32_t*)&h0; o.y = *(uint32_t*)&h1;
        o.z = *(uint32_t*)&h2; o.w = *(uint32_t*)&h3;
        ((uint4*)(g_aggh + (size_t)w * 128))[l16] = o;
    }
}

// ---------------- persistent combine: resident B, A double-buffered, ldmatrix frags ----------------
template <int OUT, bool RELU, bool HOUT, int OCC>
__global__ void __launch_bounds__(128, OCC) combine_mma(
    const uint16_t* __restrict__ Aagg,
    const uint16_t* __restrict__ Aroot,
    const uint16_t* __restrict__ Bw,
    const float* __restrict__ bias,
    void* __restrict__ Cout)
{
    constexpr int NA = OUT / 16;
    constexpr int NP = NA / 2;
    constexpr int NTILES = (N_NODES + 63) / 64;   // 782
    __shared__ uint32_t As[2][64][36];
    __shared__ uint32_t Bs[OUT][132];

    const int tid    = threadIdx.x;
    const int wid    = tid >> 5;
    const int lane   = tid & 31;
    const int warp_m = wid >> 1;
    const int warp_n = wid & 1;
    const int g      = lane >> 2;
    const int t      = lane & 3;

    const int lj = lane & 7;
    const int lk = (lane >> 3) & 1;
    const int lh = lane >> 4;
    uint32_t aBase[2];
#pragma unroll
    for (int m = 0; m < 2; m++) {
        int row = warp_m * 32 + m * 16 + lj + lk * 8;
        aBase[m] = (uint32_t)__cvta_generic_to_shared(&As[0][row][lh * 4]);
    }
    uint32_t bBase[NP];
#pragma unroll
    for (int p = 0; p < NP; p++) {
        int col = warp_n * (OUT / 2) + (p * 2 + lh) * 8 + lj;
        bBase[p] = (uint32_t)__cvta_generic_to_shared(&Bs[col][lk * 4]);
    }
    constexpr uint32_t ABUF = 64 * 36 * 4;

#pragma unroll
    for (int i = 0; i < OUT / 4; i++) {
        int idx = i * 128 + tid;
        int o = idx >> 5, q = idx & 31;
        cp16((uint32_t)__cvta_generic_to_shared(&Bs[o][q * 4]),
             Bw + (size_t)o * 256 + q * 8);
    }
    CP_COMMIT();

    auto issueA = [&](int tile, int c, int buf) {
        const int row0 = tile * 64;
        const int k0 = c * 64;
        const uint16_t* src = (k0 < 128) ? (Aagg + k0) : (Aroot + (k0 - 128));
#pragma unroll
        for (int i = 0; i < 4; i++) {
            int idx = i * 128 + tid;
            int r = idx >> 3, q = idx & 7;
            int grow = row0 + r;
            if (grow > N_NODES - 1) grow = N_NODES - 1;
            cp16((uint32_t)__cvta_generic_to_shared(&As[buf][r][q * 4]),
                 src + (size_t)grow * 128 + q * 8);
        }
        CP_COMMIT();
    };

    for (int tile = blockIdx.x; tile < NTILES; tile += gridDim.x) {
        const int row0 = tile * 64;

        float acc[2][NA][4];
#pragma unroll
        for (int m = 0; m < 2; m++)
#pragma unroll
            for (int n = 0; n < NA; n++)
#pragma unroll
                for (int j = 0; j < 4; j++) acc[m][n][j] = 0.f;

        issueA(tile, 0, 0);

        for (int c = 0; c < 4; c++) {
            if (c < 3) { issueA(tile, c + 1, (c + 1) & 1); CP_WAIT(1); }
            else       { CP_WAIT(0); }
            __syncthreads();

            const int buf = c & 1;
            const int kb  = c * 32;
#pragma unroll
            for (int ks = 0; ks < 4; ks++) {
                const int off = ks * 8;
                uint32_t a[2][4];
#pragma unroll
                for (int m = 0; m < 2; m++)
                    ldsm_x4(a[m], aBase[m] + buf * ABUF + off * 4);
                uint32_t b[NA][2];
#pragma unroll
                for (int p = 0; p < NP; p++) {
                    uint32_t br[4];
                    ldsm_x4(br, bBase[p] + (kb + off) * 4);
                    b[p * 2][0] = br[0]; b[p * 2][1] = br[1];
                    b[p * 2 + 1][0] = br[2]; b[p * 2 + 1][1] = br[3];
                }
#pragma unroll
                for (int m = 0; m < 2; m++)
#pragma unroll
                    for (int n = 0; n < NA; n++)
                        mma_f16(acc[m][n], a[m], b[n]);
            }
            __syncthreads();
        }

        // ---- epilogue ----
#pragma unroll
        for (int m = 0; m < 2; m++) {
            int r_lo = row0 + warp_m * 32 + m * 16 + g;
            int r_hi = r_lo + 8;
#pragma unroll
            for (int n = 0; n < NA; n++) {
                int col = warp_n * (OUT / 2) + n * 8 + t * 2;
                float bx = bias[col], by = bias[col + 1];
                float v0 = acc[m][n][0] + bx, v1 = acc[m][n][1] + by;
                float v2 = acc[m][n][2] + bx, v3 = acc[m][n][3] + by;
                if (RELU) {
                    v0 = fmaxf(v0, 0.f); v1 = fmaxf(v1, 0.f);
                    v2 = fmaxf(v2, 0.f); v3 = fmaxf(v3, 0.f);
                }
                if (HOUT) {
                    uint16_t* C = (uint16_t*)Cout;
                    __half2 lo = __floats2half2_rn(v0, v1);
                    __half2 hi = __floats2half2_rn(v2, v3);
                    if (r_lo < N_NODES) *(uint32_t*)(C + (size_t)r_lo * OUT + col) = *(uint32_t*)&lo;
                    if (r_hi < N_NODES) *(uint32_t*)(C + (size_t)r_hi * OUT + col) = *(uint32_t*)&hi;
                } else {
                    float* C = (float*)Cout;
                    if (r_lo < N_NODES) *(float2*)(C + (size_t)r_lo * OUT + col) = make_float2(v0, v1);
                    if (r_hi < N_NODES) *(float2*)(C + (size_t)r_hi * OUT + col) = make_float2(v2, v3);
                }
            }
        }
    }
}

// ---------------- host launch ----------------
extern "C" void kernel_launch(void* const* d_in, const int* in_sizes, int n_in,
                              void* d_out, int out_size) {
    const float* x   = (const float*)d_in[0];
    const void*  ei  = d_in[1];
    const float* w1n = (const float*)d_in[2];
    const float* w1r = (const float*)d_in[3];
    const float* b1  = (const float*)d_in[4];
    const float* w2n = (const float*)d_in[5];
    const float* w2r = (const float*)d_in[6];
    const float* b2  = (const float*)d_in[7];
    const float* w3n = (const float*)d_in[8];
    const float* w3r = (const float*)d_in[9];
    const float* b3  = (const float*)d_in[10];

    int* ideg;
    uint16_t *xh, *aggh, *h1h, *h2h, *B1, *B2, *B3;
    cudaGetSymbolAddress((void**)&ideg, g_ideg);
    cudaGetSymbolAddress((void**)&xh,   g_xh);
    cudaGetSymbolAddress((void**)&aggh, g_aggh);
    cudaGetSymbolAddress((void**)&h1h,  g_h1h);
    cudaGetSymbolAddress((void**)&h2h,  g_h2h);
    cudaGetSymbolAddress((void**)&B1,   g_B1);
    cudaGetSymbolAddress((void**)&B2,   g_B2);
    cudaGetSymbolAddress((void**)&B3,   g_B3);

    const int TPB = 256;
    const int gatherBlocks = (N_NODES * 32 + TPB - 1) / TPB;              // 6250
    const int prepBlocks   = (N_NODES * 64 + 81920 + TPB - 1) / TPB;      // 12820
    const int gemm128Grid  = 296;
    const int gemm64Grid   = 592;

    // ---- structure + CSR + prep ----
    cudaMemsetAsync(ideg, 0, 50048 * sizeof(int));
    deg_prep<<<EDGE_BLOCKS4 + prepBlocks, TPB>>>(ei, x, w1n, w1r, w2n, w2r, w3n, w3r);
    scan_one<<<196, 256>>>();
    fill_csr<<<EDGE_BLOCKS4, TPB>>>(ei);

    // ---- layer 1 ----
    gather_mean<<<gatherBlocks, TPB>>>(xh);
    combine_mma<128, true, true, 2><<<gemm128Grid, 128>>>(aggh, xh, B1, b1, h1h);

    // ---- layer 2 ----
    gather_mean<<<gatherBlocks, TPB>>>(h1h);
    combine_mma<128, true, true, 2><<<gemm128Grid, 128>>>(aggh, h1h, B2, b2, h2h);

    // ---- layer 3 ----
    gather_mean<<<gatherBlocks, TPB>>>(h2h);
    combine_mma<64, false, false, 4><<<gemm64Grid, 128>>>(aggh, h2h, B3, b3, d_out);
}